// round 5
// baseline (speedup 1.0000x reference)
#include <cuda_runtime.h>
#include <math.h>

// Problem constants
#define BATCH 2
#define SEQ   2048
#define HID   2048
#define NH    16
#define NKV   4
#define HD    128
#define ROT   64
#define NTOK  (BATCH*SEQ)      // 4096
#define QGN   (NH*HD*2)        // 4096  (q 2048 | gate 2048)
#define KVN   (NKV*HD)         // 512

// ---------------- scratch (device globals: allocation-free) ----------------
__device__ float g_qg[(size_t)NTOK * QGN];   // 64 MB : q | gate
__device__ float g_k [(size_t)NTOK * KVN];   //  8 MB
__device__ float g_v [(size_t)NTOK * KVN];   //  8 MB
__device__ float g_o [(size_t)NTOK * HID];   // 32 MB : attention out
__device__ float g_n [(size_t)NTOK * HID];   // 32 MB : rmsnorm*gate

// ---------------- generic fp32 tiled GEMM: C[M,N] = A[M,K] * B[K,N] --------
#define BM 64
#define BN 64
#define BK 16

__global__ __launch_bounds__(256) void gemm64(
    const float* __restrict__ A, const float* __restrict__ B,
    float* __restrict__ C, int M, int N, int K)
{
    __shared__ float As[BK][BM];
    __shared__ float Bs[BK][BN];

    const int tid = threadIdx.x;          // 256 threads
    const int tx  = tid & 15;             // 0..15
    const int ty  = tid >> 4;             // 0..15
    const int m0  = blockIdx.y * BM;
    const int n0  = blockIdx.x * BN;

    // loader coordinates (float4 per thread per tile)
    const int la_r = tid >> 2;            // 0..63
    const int la_c = (tid & 3) * 4;       // 0,4,8,12
    const int lb_r = tid >> 4;            // 0..15
    const int lb_c = (tid & 15) * 4;      // 0..60

    float acc[4][4];
#pragma unroll
    for (int i = 0; i < 4; i++)
#pragma unroll
        for (int j = 0; j < 4; j++) acc[i][j] = 0.0f;

    const int ty4 = ty * 4, tx4 = tx * 4;

    for (int k0 = 0; k0 < K; k0 += BK) {
        float4 av = *(const float4*)(A + (size_t)(m0 + la_r) * K + k0 + la_c);
        float4 bv = *(const float4*)(B + (size_t)(k0 + lb_r) * N + n0 + lb_c);
        __syncthreads();
        As[la_c + 0][la_r] = av.x;
        As[la_c + 1][la_r] = av.y;
        As[la_c + 2][la_r] = av.z;
        As[la_c + 3][la_r] = av.w;
        Bs[lb_r][lb_c + 0] = bv.x;
        Bs[lb_r][lb_c + 1] = bv.y;
        Bs[lb_r][lb_c + 2] = bv.z;
        Bs[lb_r][lb_c + 3] = bv.w;
        __syncthreads();
#pragma unroll
        for (int kk = 0; kk < BK; kk++) {
            float a0 = As[kk][ty4 + 0], a1 = As[kk][ty4 + 1];
            float a2 = As[kk][ty4 + 2], a3 = As[kk][ty4 + 3];
            float b0 = Bs[kk][tx4 + 0], b1 = Bs[kk][tx4 + 1];
            float b2 = Bs[kk][tx4 + 2], b3 = Bs[kk][tx4 + 3];
            acc[0][0] += a0*b0; acc[0][1] += a0*b1; acc[0][2] += a0*b2; acc[0][3] += a0*b3;
            acc[1][0] += a1*b0; acc[1][1] += a1*b1; acc[1][2] += a1*b2; acc[1][3] += a1*b3;
            acc[2][0] += a2*b0; acc[2][1] += a2*b1; acc[2][2] += a2*b2; acc[2][3] += a2*b3;
            acc[3][0] += a3*b0; acc[3][1] += a3*b1; acc[3][2] += a3*b2; acc[3][3] += a3*b3;
        }
    }

#pragma unroll
    for (int i = 0; i < 4; i++) {
        float4 r = make_float4(acc[i][0], acc[i][1], acc[i][2], acc[i][3]);
        *(float4*)(C + (size_t)(m0 + ty4 + i) * N + n0 + tx4) = r;
    }
}

// ---------------- RoPE (in-place, reference's exact quirky form) -----------
// q_out[j]    = cos[j]*q[64+j] + rh(q[0:64])[j]*sin[j]   (j<64)
// q_out[64+j] = q[64+j]
// k_out[j]    = sin[j]*k[64+j] + rh(k[0:64])[j]*sin[j]   <-- sin both terms
// rh(x)[j] = j<32 ? -x[j+32] : x[j-32]
__global__ void rope_kernel(const float* __restrict__ cosb,
                            const float* __restrict__ sinb)
{
    const int t    = blockIdx.x;        // token
    const int head = blockIdx.y;        // 0..NH-1 = q heads, NH..NH+NKV-1 = kv
    const int j    = threadIdx.x;       // 0..63
    __shared__ float sh[ROT];

    float* base;
    if (head < NH) base = g_qg + (size_t)t * QGN + head * HD;
    else           base = g_k  + (size_t)t * KVN + (head - NH) * HD;

    sh[j] = base[j];
    float pass = base[ROT + j];
    __syncthreads();
    float rh = (j < 32) ? -sh[j + 32] : sh[j - 32];
    float c  = cosb[(size_t)t * ROT + j];
    float sn = sinb[(size_t)t * ROT + j];
    float o  = (head < NH) ? (c * pass + rh * sn) : (sn * pass + rh * sn);
    base[j] = o;
}

// ---------------- flash attention (causal, GQA) ----------------------------
#define SQ 132          // padded row stride for 128-wide tiles
#define SP 68           // padded row stride for 64-wide P tile
#define ATT_SMEM ((3 * 64 * SQ + 64 * SP) * 4)   // 118784 B

__global__ __launch_bounds__(256) void attn_kernel()
{
    extern __shared__ float sm[];
    float* Qs = sm;                  // [64][SQ]
    float* Ks = Qs + 64 * SQ;        // [64][SQ]
    float* Vs = Ks + 64 * SQ;        // [64][SQ]
    float* Ps = Vs + 64 * SQ;        // [64][SP]

    const int qt = blockIdx.x;       // q tile (64 rows)
    const int h  = blockIdx.y;
    const int b  = blockIdx.z;
    const int kvh = h / (NH / NKV);

    const int tid = threadIdx.x;
    const int tx  = tid & 15;        // score cols tx*4.., O cols tx*8..
    const int ty  = tid >> 4;        // rows ty*4..

    // load Q tile [64 x 128]
    const float* Qb = g_qg + (size_t)(b * SEQ + qt * 64) * QGN + h * HD;
#pragma unroll
    for (int i = 0; i < 8; i++) {
        int f4 = tid + i * 256;           // 0..2047
        int r  = f4 >> 5;
        int c  = (f4 & 31) * 4;
        float4 v = *(const float4*)(Qb + (size_t)r * QGN + c);
        Qs[r * SQ + c + 0] = v.x; Qs[r * SQ + c + 1] = v.y;
        Qs[r * SQ + c + 2] = v.z; Qs[r * SQ + c + 3] = v.w;
    }

    float m[4], l[4], o[4][8];
#pragma unroll
    for (int i = 0; i < 4; i++) {
        m[i] = -INFINITY; l[i] = 0.0f;
#pragma unroll
        for (int j = 0; j < 8; j++) o[i][j] = 0.0f;
    }
    const float scale = 0.08838834764831845f;   // 1/sqrt(128)

    for (int jt = 0; jt <= qt; jt++) {
        __syncthreads();   // prev iter done with Ks/Vs/Ps (also fences Q load)
        const float* Kb = g_k + (size_t)(b * SEQ + jt * 64) * KVN + kvh * HD;
        const float* Vb = g_v + (size_t)(b * SEQ + jt * 64) * KVN + kvh * HD;
#pragma unroll
        for (int i = 0; i < 8; i++) {
            int f4 = tid + i * 256;
            int r  = f4 >> 5;
            int c  = (f4 & 31) * 4;
            float4 kv4 = *(const float4*)(Kb + (size_t)r * KVN + c);
            Ks[r * SQ + c + 0] = kv4.x; Ks[r * SQ + c + 1] = kv4.y;
            Ks[r * SQ + c + 2] = kv4.z; Ks[r * SQ + c + 3] = kv4.w;
            float4 vv4 = *(const float4*)(Vb + (size_t)r * KVN + c);
            Vs[r * SQ + c + 0] = vv4.x; Vs[r * SQ + c + 1] = vv4.y;
            Vs[r * SQ + c + 2] = vv4.z; Vs[r * SQ + c + 3] = vv4.w;
        }
        __syncthreads();

        // scores: S[4][4] = Q(rows ty*4..) . K(rows tx*4..)^T
        float s[4][4];
#pragma unroll
        for (int i = 0; i < 4; i++)
#pragma unroll
            for (int j = 0; j < 4; j++) s[i][j] = 0.0f;

        for (int kk = 0; kk < HD; kk += 4) {
            float4 qv[4], kv[4];
#pragma unroll
            for (int i = 0; i < 4; i++)
                qv[i] = *(const float4*)&Qs[(ty * 4 + i) * SQ + kk];
#pragma unroll
            for (int j = 0; j < 4; j++)
                kv[j] = *(const float4*)&Ks[(tx * 4 + j) * SQ + kk];
#pragma unroll
            for (int i = 0; i < 4; i++)
#pragma unroll
                for (int j = 0; j < 4; j++)
                    s[i][j] += qv[i].x * kv[j].x + qv[i].y * kv[j].y +
                               qv[i].z * kv[j].z + qv[i].w * kv[j].w;
        }

        // scale + causal mask (diagonal tile only)
#pragma unroll
        for (int i = 0; i < 4; i++)
#pragma unroll
            for (int j = 0; j < 4; j++) {
                float v = s[i][j] * scale;
                if (jt == qt && (tx * 4 + j) > (ty * 4 + i)) v = -1.0e9f;
                s[i][j] = v;
            }

        // online softmax per row (16 lanes share a row group)
#pragma unroll
        for (int i = 0; i < 4; i++) {
            float tmax = fmaxf(fmaxf(s[i][0], s[i][1]), fmaxf(s[i][2], s[i][3]));
#pragma unroll
            for (int off = 8; off >= 1; off >>= 1)
                tmax = fmaxf(tmax, __shfl_xor_sync(0xffffffffu, tmax, off));
            float mn = fmaxf(m[i], tmax);
            float sc = expf(m[i] - mn);
            float rs = 0.0f;
#pragma unroll
            for (int j = 0; j < 4; j++) {
                float p = expf(s[i][j] - mn);
                s[i][j] = p;
                rs += p;
            }
#pragma unroll
            for (int off = 8; off >= 1; off >>= 1)
                rs += __shfl_xor_sync(0xffffffffu, rs, off);
            l[i] = l[i] * sc + rs;
            m[i] = mn;
#pragma unroll
            for (int j = 0; j < 8; j++) o[i][j] *= sc;
        }

        // stash P, then O += P @ V
#pragma unroll
        for (int i = 0; i < 4; i++)
#pragma unroll
            for (int j = 0; j < 4; j++)
                Ps[(ty * 4 + i) * SP + tx * 4 + j] = s[i][j];
        __syncthreads();

        for (int kc = 0; kc < 64; kc++) {
            float4 va = *(const float4*)&Vs[kc * SQ + tx * 8];
            float4 vb = *(const float4*)&Vs[kc * SQ + tx * 8 + 4];
#pragma unroll
            for (int i = 0; i < 4; i++) {
                float p = Ps[(ty * 4 + i) * SP + kc];
                o[i][0] += p * va.x; o[i][1] += p * va.y;
                o[i][2] += p * va.z; o[i][3] += p * va.w;
                o[i][4] += p * vb.x; o[i][5] += p * vb.y;
                o[i][6] += p * vb.z; o[i][7] += p * vb.w;
            }
        }
    }

    // write normalized output: g_o[token][h*128 + d]
#pragma unroll
    for (int i = 0; i < 4; i++) {
        float inv = 1.0f / l[i];
        size_t base = (size_t)(b * SEQ + qt * 64 + ty * 4 + i) * HID + h * HD + tx * 8;
#pragma unroll
        for (int j = 0; j < 8; j++)
            g_o[base + j] = o[i][j] * inv;
    }
}

// ---------------- rmsnorm * (1+w) * sigmoid(gate) --------------------------
__global__ __launch_bounds__(256) void norm_gate_kernel(const float* __restrict__ nw)
{
    const int t   = blockIdx.x;
    const int tid = threadIdx.x;
    const float* o    = g_o  + (size_t)t * HID;
    const float* gate = g_qg + (size_t)t * QGN + 2048;

    float vals[8];
    float ss = 0.0f;
#pragma unroll
    for (int i = 0; i < 8; i++) {
        float v = o[tid + i * 256];
        vals[i] = v;
        ss += v * v;
    }
#pragma unroll
    for (int off = 16; off >= 1; off >>= 1)
        ss += __shfl_xor_sync(0xffffffffu, ss, off);

    __shared__ float red[8];
    if ((tid & 31) == 0) red[tid >> 5] = ss;
    __syncthreads();
    float tot = red[0] + red[1] + red[2] + red[3] + red[4] + red[5] + red[6] + red[7];
    float r = rsqrtf(tot / (float)HID + 1e-6f);

#pragma unroll
    for (int i = 0; i < 8; i++) {
        int j = tid + i * 256;
        float gt = gate[j];
        float sg = 1.0f / (1.0f + expf(-gt));
        g_n[(size_t)t * HID + j] = vals[i] * r * (1.0f + nw[j]) * sg;
    }
}

// ---------------- launch ---------------------------------------------------
extern "C" void kernel_launch(void* const* d_in, const int* in_sizes, int n_in,
                              void* d_out, int out_size)
{
    const float* hs   = (const float*)d_in[0];   // hidden_states [2,2048,2048]
    const float* cosb = (const float*)d_in[1];   // cos [2,2048,64]
    const float* sinb = (const float*)d_in[2];   // sin [2,2048,64]
    // d_in[3] = attention_mask (causal, reproduced analytically)
    const float* Wq   = (const float*)d_in[4];   // [2048,4096]
    const float* Wk   = (const float*)d_in[5];   // [2048,512]
    const float* Wv   = (const float*)d_in[6];   // [2048,512]
    const float* Wo   = (const float*)d_in[7];   // [2048,2048]
    const float* nw   = (const float*)d_in[8];   // [2048]
    float* out = (float*)d_out;

    float *qg, *kb, *vb, *nb;
    cudaGetSymbolAddress((void**)&qg, g_qg);
    cudaGetSymbolAddress((void**)&kb, g_k);
    cudaGetSymbolAddress((void**)&vb, g_v);
    cudaGetSymbolAddress((void**)&nb, g_n);

    dim3 blk(256);

    // 1) projections
    gemm64<<<dim3(QGN / BN, NTOK / BM), blk>>>(hs, Wq, qg, NTOK, QGN, HID);
    gemm64<<<dim3(KVN / BN, NTOK / BM), blk>>>(hs, Wk, kb, NTOK, KVN, HID);
    gemm64<<<dim3(KVN / BN, NTOK / BM), blk>>>(hs, Wv, vb, NTOK, KVN, HID);

    // 2) rope (in-place on q part of g_qg and on g_k)
    rope_kernel<<<dim3(NTOK, NH + NKV), ROT>>>(cosb, sinb);

    // 3) flash attention (attribute persists; idempotent per-call set)
    cudaFuncSetAttribute(attn_kernel, cudaFuncAttributeMaxDynamicSharedMemorySize, ATT_SMEM);
    attn_kernel<<<dim3(SEQ / 64, NH, BATCH), blk, ATT_SMEM>>>();

    // 4) rmsnorm * sigmoid(gate)
    norm_gate_kernel<<<NTOK, blk>>>(nw);

    // 5) output projection
    gemm64<<<dim3(HID / BN, NTOK / BM), blk>>>(nb, Wo, out, NTOK, HID, HID);
}

// round 6
// speedup vs baseline: 1.6322x; 1.6322x over previous
#include <cuda_runtime.h>
#include <math.h>

// Problem constants
#define BATCH 2
#define SEQ   2048
#define HID   2048
#define NH    16
#define NKV   4
#define HD    128
#define ROT   64
#define NTOK  (BATCH*SEQ)      // 4096
#define QGN   (NH*HD*2)        // 4096  (q 2048 | gate 2048)
#define KVN   (NKV*HD)         // 512

// ---------------- scratch (device globals: allocation-free) ----------------
__device__ float g_qg[(size_t)NTOK * QGN];   // 64 MB : q | gate
__device__ float g_k [(size_t)NTOK * KVN];   //  8 MB
__device__ float g_v [(size_t)NTOK * KVN];   //  8 MB
__device__ float g_o [(size_t)NTOK * HID];   // 32 MB : attention out
__device__ float g_n [(size_t)NTOK * HID];   // 32 MB : rmsnorm*gate

// =================== tf32 tensor-core GEMM: C = A[M,K] @ B[K,N] ============
// CTA tile 128x128x16, 8 warps, warp tile 64x32 (4x4 of m16n8k8 mma).
#define TBM 128
#define TBN 128
#define TBK 16
#define APAD 8     // stride 136: 136%32==8 -> conflict-free fragment loads
#define BPAD 8

__device__ __forceinline__ unsigned f2tf32(float x) {
    unsigned u;
    asm("cvt.rna.tf32.f32 %0, %1;" : "=r"(u) : "f"(x));
    return u;
}

__global__ __launch_bounds__(256) void gemm_tf32(
    const float* __restrict__ A, const float* __restrict__ B,
    float* __restrict__ C, int M, int N, int K)
{
    __shared__ float As[TBK][TBM + APAD];   // As[k][m]
    __shared__ float Bs[TBK][TBN + BPAD];   // Bs[k][n]

    const int tid    = threadIdx.x;
    const int lane   = tid & 31;
    const int wid    = tid >> 5;
    const int warp_m = (wid >> 2) * 64;     // 0, 64
    const int warp_n = (wid & 3)  * 32;     // 0,32,64,96
    const int grp    = lane >> 2;           // 0..7
    const int tg     = lane & 3;            // 0..3

    const int m0 = blockIdx.y * TBM;
    const int n0 = blockIdx.x * TBN;

    // global loader coords
    const int a_r = tid >> 2;               // 0..63
    const int a_c = (tid & 3) * 4;          // 0,4,8,12
    const int b_r = tid >> 5;               // 0..7
    const int b_c = (tid & 31) * 4;         // 0..124

    float acc[4][4][4];
#pragma unroll
    for (int i = 0; i < 4; i++)
#pragma unroll
        for (int j = 0; j < 4; j++)
#pragma unroll
            for (int c = 0; c < 4; c++) acc[i][j][c] = 0.0f;

    for (int k0 = 0; k0 < K; k0 += TBK) {
        float4 av0 = *(const float4*)(A + (size_t)(m0 + a_r)      * K + k0 + a_c);
        float4 av1 = *(const float4*)(A + (size_t)(m0 + a_r + 64) * K + k0 + a_c);
        float4 bv0 = *(const float4*)(B + (size_t)(k0 + b_r)      * N + n0 + b_c);
        float4 bv1 = *(const float4*)(B + (size_t)(k0 + b_r + 8)  * N + n0 + b_c);
        __syncthreads();
        As[a_c + 0][a_r]      = __uint_as_float(f2tf32(av0.x));
        As[a_c + 1][a_r]      = __uint_as_float(f2tf32(av0.y));
        As[a_c + 2][a_r]      = __uint_as_float(f2tf32(av0.z));
        As[a_c + 3][a_r]      = __uint_as_float(f2tf32(av0.w));
        As[a_c + 0][a_r + 64] = __uint_as_float(f2tf32(av1.x));
        As[a_c + 1][a_r + 64] = __uint_as_float(f2tf32(av1.y));
        As[a_c + 2][a_r + 64] = __uint_as_float(f2tf32(av1.z));
        As[a_c + 3][a_r + 64] = __uint_as_float(f2tf32(av1.w));
        Bs[b_r][b_c + 0]     = __uint_as_float(f2tf32(bv0.x));
        Bs[b_r][b_c + 1]     = __uint_as_float(f2tf32(bv0.y));
        Bs[b_r][b_c + 2]     = __uint_as_float(f2tf32(bv0.z));
        Bs[b_r][b_c + 3]     = __uint_as_float(f2tf32(bv0.w));
        Bs[b_r + 8][b_c + 0] = __uint_as_float(f2tf32(bv1.x));
        Bs[b_r + 8][b_c + 1] = __uint_as_float(f2tf32(bv1.y));
        Bs[b_r + 8][b_c + 2] = __uint_as_float(f2tf32(bv1.z));
        Bs[b_r + 8][b_c + 3] = __uint_as_float(f2tf32(bv1.w));
        __syncthreads();

#pragma unroll
        for (int ks = 0; ks < TBK; ks += 8) {
            unsigned a[4][4], bfr[4][2];
#pragma unroll
            for (int mi = 0; mi < 4; mi++) {
                int mb = warp_m + mi * 16;
                a[mi][0] = __float_as_uint(As[ks + tg    ][mb + grp    ]);
                a[mi][1] = __float_as_uint(As[ks + tg    ][mb + grp + 8]);
                a[mi][2] = __float_as_uint(As[ks + tg + 4][mb + grp    ]);
                a[mi][3] = __float_as_uint(As[ks + tg + 4][mb + grp + 8]);
            }
#pragma unroll
            for (int nj = 0; nj < 4; nj++) {
                int nb = warp_n + nj * 8;
                bfr[nj][0] = __float_as_uint(Bs[ks + tg    ][nb + grp]);
                bfr[nj][1] = __float_as_uint(Bs[ks + tg + 4][nb + grp]);
            }
#pragma unroll
            for (int mi = 0; mi < 4; mi++)
#pragma unroll
                for (int nj = 0; nj < 4; nj++) {
                    asm volatile(
                        "mma.sync.aligned.m16n8k8.row.col.f32.tf32.tf32.f32 "
                        "{%0,%1,%2,%3}, {%4,%5,%6,%7}, {%8,%9}, {%0,%1,%2,%3};\n"
                        : "+f"(acc[mi][nj][0]), "+f"(acc[mi][nj][1]),
                          "+f"(acc[mi][nj][2]), "+f"(acc[mi][nj][3])
                        : "r"(a[mi][0]), "r"(a[mi][1]), "r"(a[mi][2]), "r"(a[mi][3]),
                          "r"(bfr[nj][0]), "r"(bfr[nj][1]));
                }
        }
    }

#pragma unroll
    for (int mi = 0; mi < 4; mi++)
#pragma unroll
        for (int nj = 0; nj < 4; nj++) {
            int row = m0 + warp_m + mi * 16 + grp;
            int col = n0 + warp_n + nj * 8 + 2 * tg;
            *(float2*)(C + (size_t)row * N + col) =
                make_float2(acc[mi][nj][0], acc[mi][nj][1]);
            *(float2*)(C + (size_t)(row + 8) * N + col) =
                make_float2(acc[mi][nj][2], acc[mi][nj][3]);
        }
}

// ---------------- RoPE (in-place, reference's exact quirky form) -----------
__global__ void rope_kernel(const float* __restrict__ cosb,
                            const float* __restrict__ sinb)
{
    const int t    = blockIdx.x;        // token
    const int head = blockIdx.y;        // 0..NH-1 = q heads, NH..NH+NKV-1 = kv
    const int j    = threadIdx.x;       // 0..63
    __shared__ float sh[ROT];

    float* base;
    if (head < NH) base = g_qg + (size_t)t * QGN + head * HD;
    else           base = g_k  + (size_t)t * KVN + (head - NH) * HD;

    sh[j] = base[j];
    float pass = base[ROT + j];
    __syncthreads();
    float rh = (j < 32) ? -sh[j + 32] : sh[j - 32];
    float c  = cosb[(size_t)t * ROT + j];
    float sn = sinb[(size_t)t * ROT + j];
    float o  = (head < NH) ? (c * pass + rh * sn) : (sn * pass + rh * sn);
    base[j] = o;
}

// ---------------- flash attention (causal, GQA) ----------------------------
#define SQ 132          // padded row stride for 128-wide tiles
#define SP 68           // padded row stride for 64-wide P tile
#define ATT_SMEM ((3 * 64 * SQ + 64 * SP) * 4)   // 118784 B

__global__ __launch_bounds__(256) void attn_kernel()
{
    extern __shared__ float sm[];
    float* Qs = sm;                  // [64][SQ]
    float* Ks = Qs + 64 * SQ;        // [64][SQ]
    float* Vs = Ks + 64 * SQ;        // [64][SQ]
    float* Ps = Vs + 64 * SQ;        // [64][SP]

    const int qt = blockIdx.x;       // q tile (64 rows)
    const int h  = blockIdx.y;
    const int b  = blockIdx.z;
    const int kvh = h / (NH / NKV);

    const int tid = threadIdx.x;
    const int tx  = tid & 15;        // score cols tx*4.., O cols tx*8..
    const int ty  = tid >> 4;        // rows ty*4..

    // load Q tile [64 x 128]
    const float* Qb = g_qg + (size_t)(b * SEQ + qt * 64) * QGN + h * HD;
#pragma unroll
    for (int i = 0; i < 8; i++) {
        int f4 = tid + i * 256;           // 0..2047
        int r  = f4 >> 5;
        int c  = (f4 & 31) * 4;
        float4 v = *(const float4*)(Qb + (size_t)r * QGN + c);
        Qs[r * SQ + c + 0] = v.x; Qs[r * SQ + c + 1] = v.y;
        Qs[r * SQ + c + 2] = v.z; Qs[r * SQ + c + 3] = v.w;
    }

    float m[4], l[4], o[4][8];
#pragma unroll
    for (int i = 0; i < 4; i++) {
        m[i] = -INFINITY; l[i] = 0.0f;
#pragma unroll
        for (int j = 0; j < 8; j++) o[i][j] = 0.0f;
    }
    const float scale = 0.08838834764831845f;   // 1/sqrt(128)

    for (int jt = 0; jt <= qt; jt++) {
        __syncthreads();   // prev iter done with Ks/Vs/Ps (also fences Q load)
        const float* Kb = g_k + (size_t)(b * SEQ + jt * 64) * KVN + kvh * HD;
        const float* Vb = g_v + (size_t)(b * SEQ + jt * 64) * KVN + kvh * HD;
#pragma unroll
        for (int i = 0; i < 8; i++) {
            int f4 = tid + i * 256;
            int r  = f4 >> 5;
            int c  = (f4 & 31) * 4;
            float4 kv4 = *(const float4*)(Kb + (size_t)r * KVN + c);
            Ks[r * SQ + c + 0] = kv4.x; Ks[r * SQ + c + 1] = kv4.y;
            Ks[r * SQ + c + 2] = kv4.z; Ks[r * SQ + c + 3] = kv4.w;
            float4 vv4 = *(const float4*)(Vb + (size_t)r * KVN + c);
            Vs[r * SQ + c + 0] = vv4.x; Vs[r * SQ + c + 1] = vv4.y;
            Vs[r * SQ + c + 2] = vv4.z; Vs[r * SQ + c + 3] = vv4.w;
        }
        __syncthreads();

        // scores: S[4][4] = Q(rows ty*4..) . K(rows tx*4..)^T
        float s[4][4];
#pragma unroll
        for (int i = 0; i < 4; i++)
#pragma unroll
            for (int j = 0; j < 4; j++) s[i][j] = 0.0f;

        for (int kk = 0; kk < HD; kk += 4) {
            float4 qv[4], kv[4];
#pragma unroll
            for (int i = 0; i < 4; i++)
                qv[i] = *(const float4*)&Qs[(ty * 4 + i) * SQ + kk];
#pragma unroll
            for (int j = 0; j < 4; j++)
                kv[j] = *(const float4*)&Ks[(tx * 4 + j) * SQ + kk];
#pragma unroll
            for (int i = 0; i < 4; i++)
#pragma unroll
                for (int j = 0; j < 4; j++)
                    s[i][j] += qv[i].x * kv[j].x + qv[i].y * kv[j].y +
                               qv[i].z * kv[j].z + qv[i].w * kv[j].w;
        }

        // scale + causal mask (diagonal tile only)
#pragma unroll
        for (int i = 0; i < 4; i++)
#pragma unroll
            for (int j = 0; j < 4; j++) {
                float v = s[i][j] * scale;
                if (jt == qt && (tx * 4 + j) > (ty * 4 + i)) v = -1.0e9f;
                s[i][j] = v;
            }

        // online softmax per row (16 lanes share a row group)
#pragma unroll
        for (int i = 0; i < 4; i++) {
            float tmax = fmaxf(fmaxf(s[i][0], s[i][1]), fmaxf(s[i][2], s[i][3]));
#pragma unroll
            for (int off = 8; off >= 1; off >>= 1)
                tmax = fmaxf(tmax, __shfl_xor_sync(0xffffffffu, tmax, off));
            float mn = fmaxf(m[i], tmax);
            float sc = expf(m[i] - mn);
            float rs = 0.0f;
#pragma unroll
            for (int j = 0; j < 4; j++) {
                float p = expf(s[i][j] - mn);
                s[i][j] = p;
                rs += p;
            }
#pragma unroll
            for (int off = 8; off >= 1; off >>= 1)
                rs += __shfl_xor_sync(0xffffffffu, rs, off);
            l[i] = l[i] * sc + rs;
            m[i] = mn;
#pragma unroll
            for (int j = 0; j < 8; j++) o[i][j] *= sc;
        }

        // stash P, then O += P @ V
#pragma unroll
        for (int i = 0; i < 4; i++)
#pragma unroll
            for (int j = 0; j < 4; j++)
                Ps[(ty * 4 + i) * SP + tx * 4 + j] = s[i][j];
        __syncthreads();

        for (int kc = 0; kc < 64; kc++) {
            float4 va = *(const float4*)&Vs[kc * SQ + tx * 8];
            float4 vb = *(const float4*)&Vs[kc * SQ + tx * 8 + 4];
#pragma unroll
            for (int i = 0; i < 4; i++) {
                float p = Ps[(ty * 4 + i) * SP + kc];
                o[i][0] += p * va.x; o[i][1] += p * va.y;
                o[i][2] += p * va.z; o[i][3] += p * va.w;
                o[i][4] += p * vb.x; o[i][5] += p * vb.y;
                o[i][6] += p * vb.z; o[i][7] += p * vb.w;
            }
        }
    }

    // write normalized output: g_o[token][h*128 + d]
#pragma unroll
    for (int i = 0; i < 4; i++) {
        float inv = 1.0f / l[i];
        size_t base = (size_t)(b * SEQ + qt * 64 + ty * 4 + i) * HID + h * HD + tx * 8;
#pragma unroll
        for (int j = 0; j < 8; j++)
            g_o[base + j] = o[i][j] * inv;
    }
}

// ---------------- rmsnorm * (1+w) * sigmoid(gate) --------------------------
__global__ __launch_bounds__(256) void norm_gate_kernel(const float* __restrict__ nw)
{
    const int t   = blockIdx.x;
    const int tid = threadIdx.x;
    const float* o    = g_o  + (size_t)t * HID;
    const float* gate = g_qg + (size_t)t * QGN + 2048;

    float vals[8];
    float ss = 0.0f;
#pragma unroll
    for (int i = 0; i < 8; i++) {
        float v = o[tid + i * 256];
        vals[i] = v;
        ss += v * v;
    }
#pragma unroll
    for (int off = 16; off >= 1; off >>= 1)
        ss += __shfl_xor_sync(0xffffffffu, ss, off);

    __shared__ float red[8];
    if ((tid & 31) == 0) red[tid >> 5] = ss;
    __syncthreads();
    float tot = red[0] + red[1] + red[2] + red[3] + red[4] + red[5] + red[6] + red[7];
    float r = rsqrtf(tot / (float)HID + 1e-6f);

#pragma unroll
    for (int i = 0; i < 8; i++) {
        int j = tid + i * 256;
        float gt = gate[j];
        float sg = 1.0f / (1.0f + expf(-gt));
        g_n[(size_t)t * HID + j] = vals[i] * r * (1.0f + nw[j]) * sg;
    }
}

// ---------------- launch ---------------------------------------------------
extern "C" void kernel_launch(void* const* d_in, const int* in_sizes, int n_in,
                              void* d_out, int out_size)
{
    const float* hs   = (const float*)d_in[0];   // hidden_states [2,2048,2048]
    const float* cosb = (const float*)d_in[1];   // cos [2,2048,64]
    const float* sinb = (const float*)d_in[2];   // sin [2,2048,64]
    // d_in[3] = attention_mask (causal, reproduced analytically)
    const float* Wq   = (const float*)d_in[4];   // [2048,4096]
    const float* Wk   = (const float*)d_in[5];   // [2048,512]
    const float* Wv   = (const float*)d_in[6];   // [2048,512]
    const float* Wo   = (const float*)d_in[7];   // [2048,2048]
    const float* nw   = (const float*)d_in[8];   // [2048]
    float* out = (float*)d_out;

    float *qg, *kb, *vb, *nb;
    cudaGetSymbolAddress((void**)&qg, g_qg);
    cudaGetSymbolAddress((void**)&kb, g_k);
    cudaGetSymbolAddress((void**)&vb, g_v);
    cudaGetSymbolAddress((void**)&nb, g_n);

    dim3 blk(256);

    // 1) projections (tf32 tensor cores)
    gemm_tf32<<<dim3(QGN / TBN, NTOK / TBM), blk>>>(hs, Wq, qg, NTOK, QGN, HID);
    gemm_tf32<<<dim3(KVN / TBN, NTOK / TBM), blk>>>(hs, Wk, kb, NTOK, KVN, HID);
    gemm_tf32<<<dim3(KVN / TBN, NTOK / TBM), blk>>>(hs, Wv, vb, NTOK, KVN, HID);

    // 2) rope (in-place on q part of g_qg and on g_k)
    rope_kernel<<<dim3(NTOK, NH + NKV), ROT>>>(cosb, sinb);

    // 3) flash attention
    cudaFuncSetAttribute(attn_kernel, cudaFuncAttributeMaxDynamicSharedMemorySize, ATT_SMEM);
    attn_kernel<<<dim3(SEQ / 64, NH, BATCH), blk, ATT_SMEM>>>();

    // 4) rmsnorm * sigmoid(gate)
    norm_gate_kernel<<<NTOK, blk>>>(nw);

    // 5) output projection (tf32 tensor cores)
    gemm_tf32<<<dim3(HID / TBN, NTOK / TBM), blk>>>(nb, Wo, out, NTOK, HID, HID);
}

// round 7
// speedup vs baseline: 3.1488x; 1.9292x over previous
#include <cuda_runtime.h>
#include <math.h>

// Problem constants
#define BATCH 2
#define SEQ   2048
#define HID   2048
#define NH    16
#define NKV   4
#define HD    128
#define ROT   64
#define NTOK  (BATCH*SEQ)      // 4096
#define QGN   (NH*HD*2)        // 4096  (q 2048 | gate 2048)
#define KVN   (NKV*HD)         // 512

// ---------------- scratch (device globals: allocation-free) ----------------
__device__ float g_qg[(size_t)NTOK * QGN];   // 64 MB : q | gate
__device__ float g_k [(size_t)NTOK * KVN];   //  8 MB
__device__ float g_v [(size_t)NTOK * KVN];   //  8 MB
__device__ float g_o [(size_t)NTOK * HID];   // 32 MB : attention out
__device__ float g_n [(size_t)NTOK * HID];   // 32 MB : rmsnorm*gate

__device__ __forceinline__ unsigned f2tf32(float x) {
    unsigned u;
    asm("cvt.rna.tf32.f32 %0, %1;" : "=r"(u) : "f"(x));
    return u;
}

#define MMA_TF32(d0,d1,d2,d3,a0,a1,a2,a3,b0,b1) \
    asm volatile( \
        "mma.sync.aligned.m16n8k8.row.col.f32.tf32.tf32.f32 " \
        "{%0,%1,%2,%3}, {%4,%5,%6,%7}, {%8,%9}, {%0,%1,%2,%3};\n" \
        : "+f"(d0), "+f"(d1), "+f"(d2), "+f"(d3) \
        : "r"(a0), "r"(a1), "r"(a2), "r"(a3), "r"(b0), "r"(b1))

// =================== tf32 tensor-core GEMM: C = A[M,K] @ B[K,N] ============
#define TBM 128
#define TBN 128
#define TBK 16
#define APAD 8
#define BPAD 8

__global__ __launch_bounds__(256) void gemm_tf32(
    const float* __restrict__ A, const float* __restrict__ B,
    float* __restrict__ C, int M, int N, int K)
{
    __shared__ float As[TBK][TBM + APAD];   // As[k][m]
    __shared__ float Bs[TBK][TBN + BPAD];   // Bs[k][n]

    const int tid    = threadIdx.x;
    const int lane   = tid & 31;
    const int wid    = tid >> 5;
    const int warp_m = (wid >> 2) * 64;
    const int warp_n = (wid & 3)  * 32;
    const int grp    = lane >> 2;
    const int tg     = lane & 3;

    const int m0 = blockIdx.y * TBM;
    const int n0 = blockIdx.x * TBN;

    const int a_r = tid >> 2;
    const int a_c = (tid & 3) * 4;
    const int b_r = tid >> 5;
    const int b_c = (tid & 31) * 4;

    float acc[4][4][4];
#pragma unroll
    for (int i = 0; i < 4; i++)
#pragma unroll
        for (int j = 0; j < 4; j++)
#pragma unroll
            for (int c = 0; c < 4; c++) acc[i][j][c] = 0.0f;

    for (int k0 = 0; k0 < K; k0 += TBK) {
        float4 av0 = *(const float4*)(A + (size_t)(m0 + a_r)      * K + k0 + a_c);
        float4 av1 = *(const float4*)(A + (size_t)(m0 + a_r + 64) * K + k0 + a_c);
        float4 bv0 = *(const float4*)(B + (size_t)(k0 + b_r)      * N + n0 + b_c);
        float4 bv1 = *(const float4*)(B + (size_t)(k0 + b_r + 8)  * N + n0 + b_c);
        __syncthreads();
        As[a_c + 0][a_r]      = __uint_as_float(f2tf32(av0.x));
        As[a_c + 1][a_r]      = __uint_as_float(f2tf32(av0.y));
        As[a_c + 2][a_r]      = __uint_as_float(f2tf32(av0.z));
        As[a_c + 3][a_r]      = __uint_as_float(f2tf32(av0.w));
        As[a_c + 0][a_r + 64] = __uint_as_float(f2tf32(av1.x));
        As[a_c + 1][a_r + 64] = __uint_as_float(f2tf32(av1.y));
        As[a_c + 2][a_r + 64] = __uint_as_float(f2tf32(av1.z));
        As[a_c + 3][a_r + 64] = __uint_as_float(f2tf32(av1.w));
        Bs[b_r][b_c + 0]     = __uint_as_float(f2tf32(bv0.x));
        Bs[b_r][b_c + 1]     = __uint_as_float(f2tf32(bv0.y));
        Bs[b_r][b_c + 2]     = __uint_as_float(f2tf32(bv0.z));
        Bs[b_r][b_c + 3]     = __uint_as_float(f2tf32(bv0.w));
        Bs[b_r + 8][b_c + 0] = __uint_as_float(f2tf32(bv1.x));
        Bs[b_r + 8][b_c + 1] = __uint_as_float(f2tf32(bv1.y));
        Bs[b_r + 8][b_c + 2] = __uint_as_float(f2tf32(bv1.z));
        Bs[b_r + 8][b_c + 3] = __uint_as_float(f2tf32(bv1.w));
        __syncthreads();

#pragma unroll
        for (int ks = 0; ks < TBK; ks += 8) {
            unsigned a[4][4], bfr[4][2];
#pragma unroll
            for (int mi = 0; mi < 4; mi++) {
                int mb = warp_m + mi * 16;
                a[mi][0] = __float_as_uint(As[ks + tg    ][mb + grp    ]);
                a[mi][1] = __float_as_uint(As[ks + tg    ][mb + grp + 8]);
                a[mi][2] = __float_as_uint(As[ks + tg + 4][mb + grp    ]);
                a[mi][3] = __float_as_uint(As[ks + tg + 4][mb + grp + 8]);
            }
#pragma unroll
            for (int nj = 0; nj < 4; nj++) {
                int nb = warp_n + nj * 8;
                bfr[nj][0] = __float_as_uint(Bs[ks + tg    ][nb + grp]);
                bfr[nj][1] = __float_as_uint(Bs[ks + tg + 4][nb + grp]);
            }
#pragma unroll
            for (int mi = 0; mi < 4; mi++)
#pragma unroll
                for (int nj = 0; nj < 4; nj++)
                    MMA_TF32(acc[mi][nj][0], acc[mi][nj][1], acc[mi][nj][2], acc[mi][nj][3],
                             a[mi][0], a[mi][1], a[mi][2], a[mi][3],
                             bfr[nj][0], bfr[nj][1]);
        }
    }

#pragma unroll
    for (int mi = 0; mi < 4; mi++)
#pragma unroll
        for (int nj = 0; nj < 4; nj++) {
            int row = m0 + warp_m + mi * 16 + grp;
            int col = n0 + warp_n + nj * 8 + 2 * tg;
            *(float2*)(C + (size_t)row * N + col) =
                make_float2(acc[mi][nj][0], acc[mi][nj][1]);
            *(float2*)(C + (size_t)(row + 8) * N + col) =
                make_float2(acc[mi][nj][2], acc[mi][nj][3]);
        }
}

// ---------------- RoPE (in-place, reference's exact quirky form) -----------
__global__ void rope_kernel(const float* __restrict__ cosb,
                            const float* __restrict__ sinb)
{
    const int t    = blockIdx.x;
    const int head = blockIdx.y;
    const int j    = threadIdx.x;
    __shared__ float sh[ROT];

    float* base;
    if (head < NH) base = g_qg + (size_t)t * QGN + head * HD;
    else           base = g_k  + (size_t)t * KVN + (head - NH) * HD;

    sh[j] = base[j];
    float pass = base[ROT + j];
    __syncthreads();
    float rh = (j < 32) ? -sh[j + 32] : sh[j - 32];
    float c  = cosb[(size_t)t * ROT + j];
    float sn = sinb[(size_t)t * ROT + j];
    float o  = (head < NH) ? (c * pass + rh * sn) : (sn * pass + rh * sn);
    base[j] = o;
}

// =============== flash attention, tf32 tensor cores ========================
// CTA: 128 q-rows x 64 k-cols, 8 warps, warp = 16 full rows.
#define QSR 132                       // Qs/Ks row stride (floats)
#define VTR 68                        // Vt/Ps row stride
#define QS_OFF 0
#define KS_OFF (128 * QSR)            // 16896
#define VT_OFF (KS_OFF + 64 * QSR)    // 25344
#define PS_OFF (VT_OFF + 128 * VTR)   // 34048
#define ATT_SMEM ((PS_OFF + 128 * VTR) * 4)   // 171008 B

__global__ __launch_bounds__(256) void attn_mma_kernel()
{
    extern __shared__ float sm[];
    float* Qs = sm + QS_OFF;      // [128][QSR]  q rows (tf32)
    float* Ks = sm + KS_OFF;      // [64][QSR]   k rows (tf32)
    float* Vt = sm + VT_OFF;      // [128][VTR]  V transposed: Vt[d][j] (tf32)
    float* Ps = sm + PS_OFF;      // [128][VTR]  P (tf32), warp-private rows

    const int qt  = blockIdx.x;       // q tile of 128 rows
    const int h   = blockIdx.y;
    const int b   = blockIdx.z;
    const int kvh = h / (NH / NKV);

    const int tid  = threadIdx.x;
    const int lane = tid & 31;
    const int wid  = tid >> 5;
    const int grp  = lane >> 2;       // 0..7
    const int tg   = lane & 3;        // 0..3
    const int wm   = wid * 16;        // warp's row base

    // ---- load Q tile [128 x 128] as tf32 ----
    const float* Qb = g_qg + (size_t)(b * SEQ + qt * 128) * QGN + h * HD;
#pragma unroll
    for (int i = 0; i < 16; i++) {
        int f4 = tid + i * 256;           // 0..4095
        int r  = f4 >> 5;                 // 0..127
        int c  = (f4 & 31) * 4;
        float4 v = *(const float4*)(Qb + (size_t)r * QGN + c);
        Qs[r * QSR + c + 0] = __uint_as_float(f2tf32(v.x));
        Qs[r * QSR + c + 1] = __uint_as_float(f2tf32(v.y));
        Qs[r * QSR + c + 2] = __uint_as_float(f2tf32(v.z));
        Qs[r * QSR + c + 3] = __uint_as_float(f2tf32(v.w));
    }

    float o[16][4];
#pragma unroll
    for (int nt = 0; nt < 16; nt++)
#pragma unroll
        for (int c = 0; c < 4; c++) o[nt][c] = 0.0f;
    float m0 = -1e30f, m1 = -1e30f, l0 = 0.0f, l1 = 0.0f;

    const float scale = 0.08838834764831845f;     // 1/sqrt(128)
    const int row_g0 = qt * 128 + wm + grp;       // thread's global rows
    const int row_g1 = row_g0 + 8;
    const int njt = 2 * qt + 2;

    for (int jt = 0; jt < njt; jt++) {
        __syncthreads();   // all warps done with prev Ks/Vt (covers Qs at jt=0)

        // ---- load K tile [64 x 128] and V tile transposed ----
        const float* Kb = g_k + (size_t)(b * SEQ + jt * 64) * KVN + kvh * HD;
        const float* Vb = g_v + (size_t)(b * SEQ + jt * 64) * KVN + kvh * HD;
#pragma unroll
        for (int i = 0; i < 8; i++) {
            int f4 = tid + i * 256;       // 0..2047
            int r  = f4 >> 5;             // 0..63  (seq pos in tile)
            int c  = (f4 & 31) * 4;       // 0..124 (d)
            float4 kv = *(const float4*)(Kb + (size_t)r * KVN + c);
            Ks[r * QSR + c + 0] = __uint_as_float(f2tf32(kv.x));
            Ks[r * QSR + c + 1] = __uint_as_float(f2tf32(kv.y));
            Ks[r * QSR + c + 2] = __uint_as_float(f2tf32(kv.z));
            Ks[r * QSR + c + 3] = __uint_as_float(f2tf32(kv.w));
            float4 vv = *(const float4*)(Vb + (size_t)r * KVN + c);
            Vt[(c + 0) * VTR + r] = __uint_as_float(f2tf32(vv.x));
            Vt[(c + 1) * VTR + r] = __uint_as_float(f2tf32(vv.y));
            Vt[(c + 2) * VTR + r] = __uint_as_float(f2tf32(vv.z));
            Vt[(c + 3) * VTR + r] = __uint_as_float(f2tf32(vv.w));
        }
        __syncthreads();

        // ---- S = Q @ K^T : warp computes rows [wm, wm+16) x 64 cols ----
        float s[8][4];
#pragma unroll
        for (int nt = 0; nt < 8; nt++)
#pragma unroll
            for (int c = 0; c < 4; c++) s[nt][c] = 0.0f;

#pragma unroll
        for (int ks = 0; ks < 16; ks++) {
            int k0 = ks * 8;
            unsigned a0 = __float_as_uint(Qs[(wm + grp)     * QSR + k0 + tg]);
            unsigned a1 = __float_as_uint(Qs[(wm + grp + 8) * QSR + k0 + tg]);
            unsigned a2 = __float_as_uint(Qs[(wm + grp)     * QSR + k0 + tg + 4]);
            unsigned a3 = __float_as_uint(Qs[(wm + grp + 8) * QSR + k0 + tg + 4]);
#pragma unroll
            for (int nt = 0; nt < 8; nt++) {
                unsigned b0 = __float_as_uint(Ks[(nt * 8 + grp) * QSR + k0 + tg]);
                unsigned b1 = __float_as_uint(Ks[(nt * 8 + grp) * QSR + k0 + tg + 4]);
                MMA_TF32(s[nt][0], s[nt][1], s[nt][2], s[nt][3], a0, a1, a2, a3, b0, b1);
            }
        }

        // ---- scale + causal mask (only the two diagonal tiles) ----
        const bool need_mask = (jt >= 2 * qt);
#pragma unroll
        for (int nt = 0; nt < 8; nt++) {
            s[nt][0] *= scale; s[nt][1] *= scale;
            s[nt][2] *= scale; s[nt][3] *= scale;
            if (need_mask) {
                int c0 = jt * 64 + nt * 8 + 2 * tg;
                if (c0     > row_g0) s[nt][0] = -1.0e9f;
                if (c0 + 1 > row_g0) s[nt][1] = -1.0e9f;
                if (c0     > row_g1) s[nt][2] = -1.0e9f;
                if (c0 + 1 > row_g1) s[nt][3] = -1.0e9f;
            }
        }

        // ---- online softmax (rows fully warp-local; reduce over quad) ----
        float mx0 = -1e30f, mx1 = -1e30f;
#pragma unroll
        for (int nt = 0; nt < 8; nt++) {
            mx0 = fmaxf(mx0, fmaxf(s[nt][0], s[nt][1]));
            mx1 = fmaxf(mx1, fmaxf(s[nt][2], s[nt][3]));
        }
        mx0 = fmaxf(mx0, __shfl_xor_sync(0xffffffffu, mx0, 1));
        mx0 = fmaxf(mx0, __shfl_xor_sync(0xffffffffu, mx0, 2));
        mx1 = fmaxf(mx1, __shfl_xor_sync(0xffffffffu, mx1, 1));
        mx1 = fmaxf(mx1, __shfl_xor_sync(0xffffffffu, mx1, 2));

        float mn0 = fmaxf(m0, mx0);
        float mn1 = fmaxf(m1, mx1);
        float sc0 = __expf(m0 - mn0);
        float sc1 = __expf(m1 - mn1);
        float rs0 = 0.0f, rs1 = 0.0f;
#pragma unroll
        for (int nt = 0; nt < 8; nt++) {
            s[nt][0] = __expf(s[nt][0] - mn0);
            s[nt][1] = __expf(s[nt][1] - mn0);
            s[nt][2] = __expf(s[nt][2] - mn1);
            s[nt][3] = __expf(s[nt][3] - mn1);
            rs0 += s[nt][0] + s[nt][1];
            rs1 += s[nt][2] + s[nt][3];
        }
        rs0 += __shfl_xor_sync(0xffffffffu, rs0, 1);
        rs0 += __shfl_xor_sync(0xffffffffu, rs0, 2);
        rs1 += __shfl_xor_sync(0xffffffffu, rs1, 1);
        rs1 += __shfl_xor_sync(0xffffffffu, rs1, 2);

        l0 = l0 * sc0 + rs0; m0 = mn0;
        l1 = l1 * sc1 + rs1; m1 = mn1;
#pragma unroll
        for (int nt = 0; nt < 16; nt++) {
            o[nt][0] *= sc0; o[nt][1] *= sc0;
            o[nt][2] *= sc1; o[nt][3] *= sc1;
        }

        // ---- stash P as tf32 (warp-private rows, no CTA sync needed) ----
#pragma unroll
        for (int nt = 0; nt < 8; nt++) {
            float2 p0 = make_float2(__uint_as_float(f2tf32(s[nt][0])),
                                    __uint_as_float(f2tf32(s[nt][1])));
            float2 p1 = make_float2(__uint_as_float(f2tf32(s[nt][2])),
                                    __uint_as_float(f2tf32(s[nt][3])));
            *(float2*)&Ps[(wm + grp)     * VTR + nt * 8 + 2 * tg] = p0;
            *(float2*)&Ps[(wm + grp + 8) * VTR + nt * 8 + 2 * tg] = p1;
        }
        __syncwarp();

        // ---- O += P @ V  (B = Vt[d][j], col-major fragment) ----
#pragma unroll
        for (int ks = 0; ks < 8; ks++) {
            int k0 = ks * 8;
            unsigned a0 = __float_as_uint(Ps[(wm + grp)     * VTR + k0 + tg]);
            unsigned a1 = __float_as_uint(Ps[(wm + grp + 8) * VTR + k0 + tg]);
            unsigned a2 = __float_as_uint(Ps[(wm + grp)     * VTR + k0 + tg + 4]);
            unsigned a3 = __float_as_uint(Ps[(wm + grp + 8) * VTR + k0 + tg + 4]);
#pragma unroll
            for (int nt = 0; nt < 16; nt++) {
                unsigned b0 = __float_as_uint(Vt[(nt * 8 + grp) * VTR + k0 + tg]);
                unsigned b1 = __float_as_uint(Vt[(nt * 8 + grp) * VTR + k0 + tg + 4]);
                MMA_TF32(o[nt][0], o[nt][1], o[nt][2], o[nt][3], a0, a1, a2, a3, b0, b1);
            }
        }
    }

    // ---- epilogue: normalize, write g_o[token][h*128 + d] ----
    float inv0 = 1.0f / l0;
    float inv1 = 1.0f / l1;
#pragma unroll
    for (int nt = 0; nt < 16; nt++) {
        int col = h * HD + nt * 8 + 2 * tg;
        *(float2*)(g_o + (size_t)(b * SEQ + row_g0 - 0) * HID + col) =
            make_float2(o[nt][0] * inv0, o[nt][1] * inv0);
        *(float2*)(g_o + (size_t)(b * SEQ + row_g1 - 0) * HID + col) =
            make_float2(o[nt][2] * inv1, o[nt][3] * inv1);
    }
}

// ---------------- rmsnorm * (1+w) * sigmoid(gate) --------------------------
__global__ __launch_bounds__(256) void norm_gate_kernel(const float* __restrict__ nw)
{
    const int t   = blockIdx.x;
    const int tid = threadIdx.x;
    const float* o    = g_o  + (size_t)t * HID;
    const float* gate = g_qg + (size_t)t * QGN + 2048;

    float vals[8];
    float ss = 0.0f;
#pragma unroll
    for (int i = 0; i < 8; i++) {
        float v = o[tid + i * 256];
        vals[i] = v;
        ss += v * v;
    }
#pragma unroll
    for (int off = 16; off >= 1; off >>= 1)
        ss += __shfl_xor_sync(0xffffffffu, ss, off);

    __shared__ float red[8];
    if ((tid & 31) == 0) red[tid >> 5] = ss;
    __syncthreads();
    float tot = red[0] + red[1] + red[2] + red[3] + red[4] + red[5] + red[6] + red[7];
    float r = rsqrtf(tot / (float)HID + 1e-6f);

#pragma unroll
    for (int i = 0; i < 8; i++) {
        int j = tid + i * 256;
        float gt = gate[j];
        float sg = 1.0f / (1.0f + expf(-gt));
        g_n[(size_t)t * HID + j] = vals[i] * r * (1.0f + nw[j]) * sg;
    }
}

// ---------------- launch ---------------------------------------------------
extern "C" void kernel_launch(void* const* d_in, const int* in_sizes, int n_in,
                              void* d_out, int out_size)
{
    const float* hs   = (const float*)d_in[0];
    const float* cosb = (const float*)d_in[1];
    const float* sinb = (const float*)d_in[2];
    // d_in[3] = attention_mask (causal, reproduced analytically)
    const float* Wq   = (const float*)d_in[4];
    const float* Wk   = (const float*)d_in[5];
    const float* Wv   = (const float*)d_in[6];
    const float* Wo   = (const float*)d_in[7];
    const float* nw   = (const float*)d_in[8];
    float* out = (float*)d_out;

    float *qg, *kb, *vb, *nb;
    cudaGetSymbolAddress((void**)&qg, g_qg);
    cudaGetSymbolAddress((void**)&kb, g_k);
    cudaGetSymbolAddress((void**)&vb, g_v);
    cudaGetSymbolAddress((void**)&nb, g_n);

    dim3 blk(256);

    // 1) projections (tf32 tensor cores)
    gemm_tf32<<<dim3(QGN / TBN, NTOK / TBM), blk>>>(hs, Wq, qg, NTOK, QGN, HID);
    gemm_tf32<<<dim3(KVN / TBN, NTOK / TBM), blk>>>(hs, Wk, kb, NTOK, KVN, HID);
    gemm_tf32<<<dim3(KVN / TBN, NTOK / TBM), blk>>>(hs, Wv, vb, NTOK, KVN, HID);

    // 2) rope (in-place on q part of g_qg and on g_k)
    rope_kernel<<<dim3(NTOK, NH + NKV), ROT>>>(cosb, sinb);

    // 3) flash attention (tf32 tensor cores)
    cudaFuncSetAttribute(attn_mma_kernel, cudaFuncAttributeMaxDynamicSharedMemorySize, ATT_SMEM);
    attn_mma_kernel<<<dim3(SEQ / 128, NH, BATCH), blk, ATT_SMEM>>>();

    // 4) rmsnorm * sigmoid(gate)
    norm_gate_kernel<<<NTOK, blk>>>(nw);

    // 5) output projection (tf32 tensor cores)
    gemm_tf32<<<dim3(HID / TBN, NTOK / TBM), blk>>>(nb, Wo, out, NTOK, HID, HID);
}

// round 11
// speedup vs baseline: 3.6576x; 1.1616x over previous
#include <cuda_runtime.h>
#include <stdint.h>
#include <math.h>

// Problem constants
#define BATCH 2
#define SEQ   2048
#define HID   2048
#define NH    16
#define NKV   4
#define HD    128
#define ROT   64
#define NTOK  (BATCH*SEQ)      // 4096
#define QGN   (NH*HD*2)        // 4096  (q 2048 | gate 2048)
#define KVN   (NKV*HD)         // 512

// ---------------- scratch (device globals: allocation-free) ----------------
__device__ float g_qg[(size_t)NTOK * QGN];   // 64 MB : q | gate
__device__ float g_k [(size_t)NTOK * KVN];   //  8 MB
__device__ float g_v [(size_t)NTOK * KVN];   //  8 MB
__device__ float g_o [(size_t)NTOK * HID];   // 32 MB : attention out
__device__ float g_n [(size_t)NTOK * HID];   // 32 MB : rmsnorm*gate

__device__ __forceinline__ unsigned f2tf32(float x) {
    unsigned u;
    asm("cvt.rna.tf32.f32 %0, %1;" : "=r"(u) : "f"(x));
    return u;
}

__device__ __forceinline__ void cp16(unsigned dst, const void* src) {
    asm volatile("cp.async.cg.shared.global [%0], [%1], 16;\n"
                 :: "r"(dst), "l"(src));
}

#define MMA_TF32(d0,d1,d2,d3,a0,a1,a2,a3,b0,b1) \
    asm volatile( \
        "mma.sync.aligned.m16n8k8.row.col.f32.tf32.tf32.f32 " \
        "{%0,%1,%2,%3}, {%4,%5,%6,%7}, {%8,%9}, {%0,%1,%2,%3};\n" \
        : "+f"(d0), "+f"(d1), "+f"(d2), "+f"(d3) \
        : "r"(a0), "r"(a1), "r"(a2), "r"(a3), "r"(b0), "r"(b1))

// =================== tf32 tensor-core GEMM: C = A[M,K] @ B[K,N] ============
// CTA 128x128x16, 8 warps (warp 64x32), 3-stage cp.async pipeline.
// blockIdx.z==1 switches to (B2, C2) -- used to fuse the Wk/Wv projections.
#define TBM 128
#define TBN 128
#define TBK 16
#define NST 3
#define ASTR 20                       // As row stride (20%32 pattern conflict-free)
#define BSTR 136                      // Bs row stride (136%32==8)
#define AS_SZ (TBM * ASTR)            // 2560 floats
#define BS_SZ (TBK * BSTR)            // 2176 floats
#define STG_SZ (AS_SZ + BS_SZ)        // 4736 floats (18944 B, 16B-aligned)
#define GEMM_SMEM (NST * STG_SZ * 4)  // 56832 B

__global__ __launch_bounds__(256) void gemm_tf32(
    const float* __restrict__ A, const float* __restrict__ B,
    float* __restrict__ C, const float* __restrict__ B2,
    float* __restrict__ C2, int M, int N, int K)
{
    extern __shared__ float gsm[];

    if (blockIdx.z == 1) { B = B2; C = C2; }

    const int tid    = threadIdx.x;
    const int lane   = tid & 31;
    const int wid    = tid >> 5;
    const int warp_m = (wid >> 2) * 64;
    const int warp_n = (wid & 3)  * 32;
    const int grp    = lane >> 2;
    const int tg     = lane & 3;

    const int m0 = blockIdx.y * TBM;
    const int n0 = blockIdx.x * TBN;

    // cp.async chunk coords (2 A-chunks + 2 B-chunks of 16B per thread per stage)
    const int ac0 = tid * 2;
    const int a_r0 = ac0 >> 2,      a_c0 = (ac0 & 3) * 4;
    const int a_r1 = (ac0+1) >> 2,  a_c1 = ((ac0+1) & 3) * 4;
    const int b_r0 = ac0 >> 5,      b_c0 = (ac0 & 31) * 4;
    const int b_r1 = (ac0+1) >> 5,  b_c1 = ((ac0+1) & 31) * 4;

    const unsigned smem_base = (unsigned)__cvta_generic_to_shared(gsm);

    float acc[4][4][4];
#pragma unroll
    for (int i = 0; i < 4; i++)
#pragma unroll
        for (int j = 0; j < 4; j++)
#pragma unroll
            for (int c = 0; c < 4; c++) acc[i][j][c] = 0.0f;

    const int niter = K / TBK;

    // prologue: prefetch stages 0,1
#pragma unroll
    for (int s = 0; s < NST - 1; s++) {
        int k0 = s * TBK;
        unsigned as = smem_base + (s * STG_SZ) * 4;
        unsigned bs = as + AS_SZ * 4;
        cp16(as + (a_r0 * ASTR + a_c0) * 4, A + (size_t)(m0 + a_r0) * K + k0 + a_c0);
        cp16(as + (a_r1 * ASTR + a_c1) * 4, A + (size_t)(m0 + a_r1) * K + k0 + a_c1);
        cp16(bs + (b_r0 * BSTR + b_c0) * 4, B + (size_t)(k0 + b_r0) * N + n0 + b_c0);
        cp16(bs + (b_r1 * BSTR + b_c1) * 4, B + (size_t)(k0 + b_r1) * N + n0 + b_c1);
        asm volatile("cp.async.commit_group;\n");
    }

    for (int it = 0; it < niter; it++) {
        // prefetch stage it+2 (empty commit keeps group accounting constant)
        if (it + NST - 1 < niter) {
            int k0 = (it + NST - 1) * TBK;
            int st = (it + NST - 1) % NST;
            unsigned as = smem_base + (st * STG_SZ) * 4;
            unsigned bs = as + AS_SZ * 4;
            cp16(as + (a_r0 * ASTR + a_c0) * 4, A + (size_t)(m0 + a_r0) * K + k0 + a_c0);
            cp16(as + (a_r1 * ASTR + a_c1) * 4, A + (size_t)(m0 + a_r1) * K + k0 + a_c1);
            cp16(bs + (b_r0 * BSTR + b_c0) * 4, B + (size_t)(k0 + b_r0) * N + n0 + b_c0);
            cp16(bs + (b_r1 * BSTR + b_c1) * 4, B + (size_t)(k0 + b_r1) * N + n0 + b_c1);
        }
        asm volatile("cp.async.commit_group;\n");
        asm volatile("cp.async.wait_group 2;\n");
        __syncthreads();

        const float* As = gsm + (it % NST) * STG_SZ;
        const float* Bs = As + AS_SZ;

#pragma unroll
        for (int ks = 0; ks < TBK; ks += 8) {
            unsigned a[4][4], bfr[4][2];
#pragma unroll
            for (int mi = 0; mi < 4; mi++) {
                int mb = warp_m + mi * 16;
                a[mi][0] = f2tf32(As[(mb + grp)     * ASTR + ks + tg]);
                a[mi][1] = f2tf32(As[(mb + grp + 8) * ASTR + ks + tg]);
                a[mi][2] = f2tf32(As[(mb + grp)     * ASTR + ks + tg + 4]);
                a[mi][3] = f2tf32(As[(mb + grp + 8) * ASTR + ks + tg + 4]);
            }
#pragma unroll
            for (int nj = 0; nj < 4; nj++) {
                int nb = warp_n + nj * 8;
                bfr[nj][0] = f2tf32(Bs[(ks + tg)     * BSTR + nb + grp]);
                bfr[nj][1] = f2tf32(Bs[(ks + tg + 4) * BSTR + nb + grp]);
            }
#pragma unroll
            for (int mi = 0; mi < 4; mi++)
#pragma unroll
                for (int nj = 0; nj < 4; nj++)
                    MMA_TF32(acc[mi][nj][0], acc[mi][nj][1], acc[mi][nj][2], acc[mi][nj][3],
                             a[mi][0], a[mi][1], a[mi][2], a[mi][3],
                             bfr[nj][0], bfr[nj][1]);
        }
        __syncthreads();   // compute done before this stage is overwritten
    }

#pragma unroll
    for (int mi = 0; mi < 4; mi++)
#pragma unroll
        for (int nj = 0; nj < 4; nj++) {
            int row = m0 + warp_m + mi * 16 + grp;
            int col = n0 + warp_n + nj * 8 + 2 * tg;
            *(float2*)(C + (size_t)row * N + col) =
                make_float2(acc[mi][nj][0], acc[mi][nj][1]);
            *(float2*)(C + (size_t)(row + 8) * N + col) =
                make_float2(acc[mi][nj][2], acc[mi][nj][3]);
        }
}

// ---------------- RoPE: warp-per-head, lane owns (j, j+32) pair ------------
__global__ __launch_bounds__(256) void rope_kernel(const float* __restrict__ cosb,
                                                   const float* __restrict__ sinb)
{
    const int t    = blockIdx.x;
    const int lane = threadIdx.x & 31;
    const int w    = threadIdx.x >> 5;

    const float c0 = cosb[(size_t)t * ROT + lane];
    const float c1 = cosb[(size_t)t * ROT + 32 + lane];
    const float s0 = sinb[(size_t)t * ROT + lane];
    const float s1 = sinb[(size_t)t * ROT + 32 + lane];

#pragma unroll
    for (int head = w; head < NH + NKV; head += 8) {
        float* base = (head < NH)
            ? g_qg + (size_t)t * QGN + head * HD
            : g_k  + (size_t)t * KVN + (head - NH) * HD;
        float x0 = base[lane];            // rot[j],    j = lane
        float x1 = base[lane + 32];       // rot[j+32]
        float p0 = base[64 + lane];       // pass[j]
        float p1 = base[96 + lane];       // pass[j+32]
        float rh0 = -x1;
        float rh1 = x0;
        float o0, o1;
        if (head < NH) { o0 = c0 * p0 + rh0 * s0; o1 = c1 * p1 + rh1 * s1; }
        else           { o0 = s0 * p0 + rh0 * s0; o1 = s1 * p1 + rh1 * s1; }
        base[lane]      = o0;
        base[lane + 32] = o1;
    }
}

// =============== flash attention, tf32 tensor cores ========================
#define QSR 132
#define VTR 68
#define QS_OFF 0
#define KS_OFF (128 * QSR)
#define VT_OFF (KS_OFF + 64 * QSR)
#define PS_OFF (VT_OFF + 128 * VTR)
#define ATT_SMEM ((PS_OFF + 128 * VTR) * 4)   // 171008 B

__global__ __launch_bounds__(256) void attn_mma_kernel()
{
    extern __shared__ float sm[];
    float* Qs = sm + QS_OFF;
    float* Ks = sm + KS_OFF;
    float* Vt = sm + VT_OFF;
    float* Ps = sm + PS_OFF;

    const int qt  = blockIdx.x;
    const int h   = blockIdx.y;
    const int b   = blockIdx.z;
    const int kvh = h / (NH / NKV);

    const int tid  = threadIdx.x;
    const int lane = tid & 31;
    const int wid  = tid >> 5;
    const int grp  = lane >> 2;
    const int tg   = lane & 3;
    const int wm   = wid * 16;

    const float* Qb = g_qg + (size_t)(b * SEQ + qt * 128) * QGN + h * HD;
#pragma unroll
    for (int i = 0; i < 16; i++) {
        int f4 = tid + i * 256;
        int r  = f4 >> 5;
        int c  = (f4 & 31) * 4;
        float4 v = *(const float4*)(Qb + (size_t)r * QGN + c);
        Qs[r * QSR + c + 0] = __uint_as_float(f2tf32(v.x));
        Qs[r * QSR + c + 1] = __uint_as_float(f2tf32(v.y));
        Qs[r * QSR + c + 2] = __uint_as_float(f2tf32(v.z));
        Qs[r * QSR + c + 3] = __uint_as_float(f2tf32(v.w));
    }

    float o[16][4];
#pragma unroll
    for (int nt = 0; nt < 16; nt++)
#pragma unroll
        for (int c = 0; c < 4; c++) o[nt][c] = 0.0f;
    float m0 = -1e30f, m1 = -1e30f, l0 = 0.0f, l1 = 0.0f;

    const float scale = 0.08838834764831845f;
    const int row_g0 = qt * 128 + wm + grp;
    const int row_g1 = row_g0 + 8;
    const int njt = 2 * qt + 2;

    for (int jt = 0; jt < njt; jt++) {
        __syncthreads();

        const float* Kb = g_k + (size_t)(b * SEQ + jt * 64) * KVN + kvh * HD;
        const float* Vb = g_v + (size_t)(b * SEQ + jt * 64) * KVN + kvh * HD;
#pragma unroll
        for (int i = 0; i < 8; i++) {
            int f4 = tid + i * 256;
            int r  = f4 >> 5;
            int c  = (f4 & 31) * 4;
            float4 kv = *(const float4*)(Kb + (size_t)r * KVN + c);
            Ks[r * QSR + c + 0] = __uint_as_float(f2tf32(kv.x));
            Ks[r * QSR + c + 1] = __uint_as_float(f2tf32(kv.y));
            Ks[r * QSR + c + 2] = __uint_as_float(f2tf32(kv.z));
            Ks[r * QSR + c + 3] = __uint_as_float(f2tf32(kv.w));
            float4 vv = *(const float4*)(Vb + (size_t)r * KVN + c);
            Vt[(c + 0) * VTR + r] = __uint_as_float(f2tf32(vv.x));
            Vt[(c + 1) * VTR + r] = __uint_as_float(f2tf32(vv.y));
            Vt[(c + 2) * VTR + r] = __uint_as_float(f2tf32(vv.z));
            Vt[(c + 3) * VTR + r] = __uint_as_float(f2tf32(vv.w));
        }
        __syncthreads();

        float s[8][4];
#pragma unroll
        for (int nt = 0; nt < 8; nt++)
#pragma unroll
            for (int c = 0; c < 4; c++) s[nt][c] = 0.0f;

#pragma unroll
        for (int ks = 0; ks < 16; ks++) {
            int k0 = ks * 8;
            unsigned a0 = __float_as_uint(Qs[(wm + grp)     * QSR + k0 + tg]);
            unsigned a1 = __float_as_uint(Qs[(wm + grp + 8) * QSR + k0 + tg]);
            unsigned a2 = __float_as_uint(Qs[(wm + grp)     * QSR + k0 + tg + 4]);
            unsigned a3 = __float_as_uint(Qs[(wm + grp + 8) * QSR + k0 + tg + 4]);
#pragma unroll
            for (int nt = 0; nt < 8; nt++) {
                unsigned b0 = __float_as_uint(Ks[(nt * 8 + grp) * QSR + k0 + tg]);
                unsigned b1 = __float_as_uint(Ks[(nt * 8 + grp) * QSR + k0 + tg + 4]);
                MMA_TF32(s[nt][0], s[nt][1], s[nt][2], s[nt][3], a0, a1, a2, a3, b0, b1);
            }
        }

        const bool need_mask = (jt >= 2 * qt);
#pragma unroll
        for (int nt = 0; nt < 8; nt++) {
            s[nt][0] *= scale; s[nt][1] *= scale;
            s[nt][2] *= scale; s[nt][3] *= scale;
            if (need_mask) {
                int c0 = jt * 64 + nt * 8 + 2 * tg;
                if (c0     > row_g0) s[nt][0] = -1.0e9f;
                if (c0 + 1 > row_g0) s[nt][1] = -1.0e9f;
                if (c0     > row_g1) s[nt][2] = -1.0e9f;
                if (c0 + 1 > row_g1) s[nt][3] = -1.0e9f;
            }
        }

        float mx0 = -1e30f, mx1 = -1e30f;
#pragma unroll
        for (int nt = 0; nt < 8; nt++) {
            mx0 = fmaxf(mx0, fmaxf(s[nt][0], s[nt][1]));
            mx1 = fmaxf(mx1, fmaxf(s[nt][2], s[nt][3]));
        }
        mx0 = fmaxf(mx0, __shfl_xor_sync(0xffffffffu, mx0, 1));
        mx0 = fmaxf(mx0, __shfl_xor_sync(0xffffffffu, mx0, 2));
        mx1 = fmaxf(mx1, __shfl_xor_sync(0xffffffffu, mx1, 1));
        mx1 = fmaxf(mx1, __shfl_xor_sync(0xffffffffu, mx1, 2));

        float mn0 = fmaxf(m0, mx0);
        float mn1 = fmaxf(m1, mx1);
        float sc0 = __expf(m0 - mn0);
        float sc1 = __expf(m1 - mn1);
        float rs0 = 0.0f, rs1 = 0.0f;
#pragma unroll
        for (int nt = 0; nt < 8; nt++) {
            s[nt][0] = __expf(s[nt][0] - mn0);
            s[nt][1] = __expf(s[nt][1] - mn0);
            s[nt][2] = __expf(s[nt][2] - mn1);
            s[nt][3] = __expf(s[nt][3] - mn1);
            rs0 += s[nt][0] + s[nt][1];
            rs1 += s[nt][2] + s[nt][3];
        }
        rs0 += __shfl_xor_sync(0xffffffffu, rs0, 1);
        rs0 += __shfl_xor_sync(0xffffffffu, rs0, 2);
        rs1 += __shfl_xor_sync(0xffffffffu, rs1, 1);
        rs1 += __shfl_xor_sync(0xffffffffu, rs1, 2);

        l0 = l0 * sc0 + rs0; m0 = mn0;
        l1 = l1 * sc1 + rs1; m1 = mn1;
#pragma unroll
        for (int nt = 0; nt < 16; nt++) {
            o[nt][0] *= sc0; o[nt][1] *= sc0;
            o[nt][2] *= sc1; o[nt][3] *= sc1;
        }

#pragma unroll
        for (int nt = 0; nt < 8; nt++) {
            float2 p0 = make_float2(__uint_as_float(f2tf32(s[nt][0])),
                                    __uint_as_float(f2tf32(s[nt][1])));
            float2 p1 = make_float2(__uint_as_float(f2tf32(s[nt][2])),
                                    __uint_as_float(f2tf32(s[nt][3])));
            *(float2*)&Ps[(wm + grp)     * VTR + nt * 8 + 2 * tg] = p0;
            *(float2*)&Ps[(wm + grp + 8) * VTR + nt * 8 + 2 * tg] = p1;
        }
        __syncwarp();

#pragma unroll
        for (int ks = 0; ks < 8; ks++) {
            int k0 = ks * 8;
            unsigned a0 = __float_as_uint(Ps[(wm + grp)     * VTR + k0 + tg]);
            unsigned a1 = __float_as_uint(Ps[(wm + grp + 8) * VTR + k0 + tg]);
            unsigned a2 = __float_as_uint(Ps[(wm + grp)     * VTR + k0 + tg + 4]);
            unsigned a3 = __float_as_uint(Ps[(wm + grp + 8) * VTR + k0 + tg + 4]);
#pragma unroll
            for (int nt = 0; nt < 16; nt++) {
                unsigned b0 = __float_as_uint(Vt[(nt * 8 + grp) * VTR + k0 + tg]);
                unsigned b1 = __float_as_uint(Vt[(nt * 8 + grp) * VTR + k0 + tg + 4]);
                MMA_TF32(o[nt][0], o[nt][1], o[nt][2], o[nt][3], a0, a1, a2, a3, b0, b1);
            }
        }
    }

    float inv0 = 1.0f / l0;
    float inv1 = 1.0f / l1;
#pragma unroll
    for (int nt = 0; nt < 16; nt++) {
        int col = h * HD + nt * 8 + 2 * tg;
        *(float2*)(g_o + (size_t)(b * SEQ + row_g0) * HID + col) =
            make_float2(o[nt][0] * inv0, o[nt][1] * inv0);
        *(float2*)(g_o + (size_t)(b * SEQ + row_g1) * HID + col) =
            make_float2(o[nt][2] * inv1, o[nt][3] * inv1);
    }
}

// ---------------- rmsnorm * (1+w) * sigmoid(gate) --------------------------
__global__ __launch_bounds__(256) void norm_gate_kernel(const float* __restrict__ nw)
{
    const int t   = blockIdx.x;
    const int tid = threadIdx.x;
    const float* o    = g_o  + (size_t)t * HID;
    const float* gate = g_qg + (size_t)t * QGN + 2048;

    float vals[8];
    float ss = 0.0f;
#pragma unroll
    for (int i = 0; i < 8; i++) {
        float v = o[tid + i * 256];
        vals[i] = v;
        ss += v * v;
    }
#pragma unroll
    for (int off = 16; off >= 1; off >>= 1)
        ss += __shfl_xor_sync(0xffffffffu, ss, off);

    __shared__ float red[8];
    if ((tid & 31) == 0) red[tid >> 5] = ss;
    __syncthreads();
    float tot = red[0] + red[1] + red[2] + red[3] + red[4] + red[5] + red[6] + red[7];
    float r = rsqrtf(tot / (float)HID + 1e-6f);

#pragma unroll
    for (int i = 0; i < 8; i++) {
        int j = tid + i * 256;
        float gt = gate[j];
        float sg = 1.0f / (1.0f + __expf(-gt));
        g_n[(size_t)t * HID + j] = vals[i] * r * (1.0f + nw[j]) * sg;
    }
}

// ---------------- launch ---------------------------------------------------
extern "C" void kernel_launch(void* const* d_in, const int* in_sizes, int n_in,
                              void* d_out, int out_size)
{
    const float* hs   = (const float*)d_in[0];
    const float* cosb = (const float*)d_in[1];
    const float* sinb = (const float*)d_in[2];
    // d_in[3] = attention_mask (causal, reproduced analytically)
    const float* Wq   = (const float*)d_in[4];
    const float* Wk   = (const float*)d_in[5];
    const float* Wv   = (const float*)d_in[6];
    const float* Wo   = (const float*)d_in[7];
    const float* nw   = (const float*)d_in[8];
    float* out = (float*)d_out;

    float *qg, *kb, *vb, *nb;
    cudaGetSymbolAddress((void**)&qg, g_qg);
    cudaGetSymbolAddress((void**)&kb, g_k);
    cudaGetSymbolAddress((void**)&vb, g_v);
    cudaGetSymbolAddress((void**)&nb, g_n);

    dim3 blk(256);

    cudaFuncSetAttribute(gemm_tf32, cudaFuncAttributeMaxDynamicSharedMemorySize, GEMM_SMEM);
    cudaFuncSetAttribute(attn_mma_kernel, cudaFuncAttributeMaxDynamicSharedMemorySize, ATT_SMEM);

    // 1) projections (tf32 tensor cores, cp.async pipelined)
    //    Wq: 32x32 grid; Wk+Wv fused into one launch via blockIdx.z
    gemm_tf32<<<dim3(QGN / TBN, NTOK / TBM, 1), blk, GEMM_SMEM>>>(
        hs, Wq, qg, Wq, qg, NTOK, QGN, HID);
    gemm_tf32<<<dim3(KVN / TBN, NTOK / TBM, 2), blk, GEMM_SMEM>>>(
        hs, Wk, kb, Wv, vb, NTOK, KVN, HID);

    // 2) rope (in-place on q part of g_qg and on g_k)
    rope_kernel<<<NTOK, blk>>>(cosb, sinb);

    // 3) flash attention (tf32 tensor cores)
    attn_mma_kernel<<<dim3(SEQ / 128, NH, BATCH), blk, ATT_SMEM>>>();

    // 4) rmsnorm * sigmoid(gate)
    norm_gate_kernel<<<NTOK, blk>>>(nw);

    // 5) output projection (tf32 tensor cores, cp.async pipelined)
    gemm_tf32<<<dim3(HID / TBN, NTOK / TBM, 1), blk, GEMM_SMEM>>>(
        nb, Wo, out, Wo, out, NTOK, HID, HID);
}

// round 12
// speedup vs baseline: 4.0326x; 1.1025x over previous
#include <cuda_runtime.h>
#include <stdint.h>
#include <math.h>

// Problem constants
#define BATCH 2
#define SEQ   2048
#define HID   2048
#define NH    16
#define NKV   4
#define HD    128
#define ROT   64
#define NTOK  (BATCH*SEQ)      // 4096
#define QGN   (NH*HD*2)        // 4096  (q 2048 | gate 2048)
#define KVN   (NKV*HD)         // 512

// ---------------- scratch (device globals: allocation-free) ----------------
__device__ float g_qg[(size_t)NTOK * QGN];   // 64 MB : q | gate
__device__ float g_k [(size_t)NTOK * KVN];   //  8 MB (tf32-rounded bits)
__device__ float g_v [(size_t)NTOK * KVN];   //  8 MB (tf32-rounded bits)
__device__ float g_o [(size_t)NTOK * HID];   // 32 MB : attention out
__device__ float g_n [(size_t)NTOK * HID];   // 32 MB : rmsnorm*gate

__device__ __forceinline__ unsigned f2tf32(float x) {
    unsigned u;
    asm("cvt.rna.tf32.f32 %0, %1;" : "=r"(u) : "f"(x));
    return u;
}

__device__ __forceinline__ void cp16(unsigned dst, const void* src) {
    asm volatile("cp.async.cg.shared.global [%0], [%1], 16;\n"
                 :: "r"(dst), "l"(src));
}

#define MMA_TF32(d0,d1,d2,d3,a0,a1,a2,a3,b0,b1) \
    asm volatile( \
        "mma.sync.aligned.m16n8k8.row.col.f32.tf32.tf32.f32 " \
        "{%0,%1,%2,%3}, {%4,%5,%6,%7}, {%8,%9}, {%0,%1,%2,%3};\n" \
        : "+f"(d0), "+f"(d1), "+f"(d2), "+f"(d3) \
        : "r"(a0), "r"(a1), "r"(a2), "r"(a3), "r"(b0), "r"(b1))

// =================== tf32 tensor-core GEMM: C = A[M,K] @ B[K,N] ============
// CTA 128x128x16, 8 warps (warp 64x32), 3-stage cp.async pipeline.
// blockIdx.z==1 switches to (B2, C2). rnd!=0 rounds output to tf32 bits.
#define TBM 128
#define TBN 128
#define TBK 16
#define NST 3
#define ASTR 20
#define BSTR 136
#define AS_SZ (TBM * ASTR)            // 2560 floats
#define BS_SZ (TBK * BSTR)            // 2176 floats
#define STG_SZ (AS_SZ + BS_SZ)        // 4736 floats
#define GEMM_SMEM (NST * STG_SZ * 4)  // 56832 B

__global__ __launch_bounds__(256) void gemm_tf32(
    const float* __restrict__ A, const float* __restrict__ B,
    float* __restrict__ C, const float* __restrict__ B2,
    float* __restrict__ C2, int M, int N, int K, int rnd)
{
    extern __shared__ float gsm[];

    if (blockIdx.z == 1) { B = B2; C = C2; }

    const int tid    = threadIdx.x;
    const int lane   = tid & 31;
    const int wid    = tid >> 5;
    const int warp_m = (wid >> 2) * 64;
    const int warp_n = (wid & 3)  * 32;
    const int grp    = lane >> 2;
    const int tg     = lane & 3;

    const int m0 = blockIdx.y * TBM;
    const int n0 = blockIdx.x * TBN;

    const int ac0 = tid * 2;
    const int a_r0 = ac0 >> 2,      a_c0 = (ac0 & 3) * 4;
    const int a_r1 = (ac0+1) >> 2,  a_c1 = ((ac0+1) & 3) * 4;
    const int b_r0 = ac0 >> 5,      b_c0 = (ac0 & 31) * 4;
    const int b_r1 = (ac0+1) >> 5,  b_c1 = ((ac0+1) & 31) * 4;

    const unsigned smem_base = (unsigned)__cvta_generic_to_shared(gsm);

    float acc[4][4][4];
#pragma unroll
    for (int i = 0; i < 4; i++)
#pragma unroll
        for (int j = 0; j < 4; j++)
#pragma unroll
            for (int c = 0; c < 4; c++) acc[i][j][c] = 0.0f;

    const int niter = K / TBK;

#pragma unroll
    for (int s = 0; s < NST - 1; s++) {
        int k0 = s * TBK;
        unsigned as = smem_base + (s * STG_SZ) * 4;
        unsigned bs = as + AS_SZ * 4;
        cp16(as + (a_r0 * ASTR + a_c0) * 4, A + (size_t)(m0 + a_r0) * K + k0 + a_c0);
        cp16(as + (a_r1 * ASTR + a_c1) * 4, A + (size_t)(m0 + a_r1) * K + k0 + a_c1);
        cp16(bs + (b_r0 * BSTR + b_c0) * 4, B + (size_t)(k0 + b_r0) * N + n0 + b_c0);
        cp16(bs + (b_r1 * BSTR + b_c1) * 4, B + (size_t)(k0 + b_r1) * N + n0 + b_c1);
        asm volatile("cp.async.commit_group;\n");
    }

    for (int it = 0; it < niter; it++) {
        if (it + NST - 1 < niter) {
            int k0 = (it + NST - 1) * TBK;
            int st = (it + NST - 1) % NST;
            unsigned as = smem_base + (st * STG_SZ) * 4;
            unsigned bs = as + AS_SZ * 4;
            cp16(as + (a_r0 * ASTR + a_c0) * 4, A + (size_t)(m0 + a_r0) * K + k0 + a_c0);
            cp16(as + (a_r1 * ASTR + a_c1) * 4, A + (size_t)(m0 + a_r1) * K + k0 + a_c1);
            cp16(bs + (b_r0 * BSTR + b_c0) * 4, B + (size_t)(k0 + b_r0) * N + n0 + b_c0);
            cp16(bs + (b_r1 * BSTR + b_c1) * 4, B + (size_t)(k0 + b_r1) * N + n0 + b_c1);
        }
        asm volatile("cp.async.commit_group;\n");
        asm volatile("cp.async.wait_group 2;\n");
        __syncthreads();

        const float* As = gsm + (it % NST) * STG_SZ;
        const float* Bs = As + AS_SZ;

#pragma unroll
        for (int ks = 0; ks < TBK; ks += 8) {
            unsigned a[4][4], bfr[4][2];
#pragma unroll
            for (int mi = 0; mi < 4; mi++) {
                int mb = warp_m + mi * 16;
                a[mi][0] = f2tf32(As[(mb + grp)     * ASTR + ks + tg]);
                a[mi][1] = f2tf32(As[(mb + grp + 8) * ASTR + ks + tg]);
                a[mi][2] = f2tf32(As[(mb + grp)     * ASTR + ks + tg + 4]);
                a[mi][3] = f2tf32(As[(mb + grp + 8) * ASTR + ks + tg + 4]);
            }
#pragma unroll
            for (int nj = 0; nj < 4; nj++) {
                int nb = warp_n + nj * 8;
                bfr[nj][0] = f2tf32(Bs[(ks + tg)     * BSTR + nb + grp]);
                bfr[nj][1] = f2tf32(Bs[(ks + tg + 4) * BSTR + nb + grp]);
            }
#pragma unroll
            for (int mi = 0; mi < 4; mi++)
#pragma unroll
                for (int nj = 0; nj < 4; nj++)
                    MMA_TF32(acc[mi][nj][0], acc[mi][nj][1], acc[mi][nj][2], acc[mi][nj][3],
                             a[mi][0], a[mi][1], a[mi][2], a[mi][3],
                             bfr[nj][0], bfr[nj][1]);
        }
        __syncthreads();
    }

#pragma unroll
    for (int mi = 0; mi < 4; mi++)
#pragma unroll
        for (int nj = 0; nj < 4; nj++) {
            int row = m0 + warp_m + mi * 16 + grp;
            int col = n0 + warp_n + nj * 8 + 2 * tg;
            float v0 = acc[mi][nj][0], v1 = acc[mi][nj][1];
            float v2 = acc[mi][nj][2], v3 = acc[mi][nj][3];
            if (rnd) {
                v0 = __uint_as_float(f2tf32(v0));
                v1 = __uint_as_float(f2tf32(v1));
                v2 = __uint_as_float(f2tf32(v2));
                v3 = __uint_as_float(f2tf32(v3));
            }
            *(float2*)(C + (size_t)row * N + col)       = make_float2(v0, v1);
            *(float2*)(C + (size_t)(row + 8) * N + col) = make_float2(v2, v3);
        }
}

// ---------------- RoPE: warp-per-head, lane owns (j, j+32) pair ------------
// K outputs are stored tf32-rounded (attention reads K bits raw).
__global__ __launch_bounds__(256) void rope_kernel(const float* __restrict__ cosb,
                                                   const float* __restrict__ sinb)
{
    const int t    = blockIdx.x;
    const int lane = threadIdx.x & 31;
    const int w    = threadIdx.x >> 5;

    const float c0 = cosb[(size_t)t * ROT + lane];
    const float c1 = cosb[(size_t)t * ROT + 32 + lane];
    const float s0 = sinb[(size_t)t * ROT + lane];
    const float s1 = sinb[(size_t)t * ROT + 32 + lane];

#pragma unroll
    for (int head = w; head < NH + NKV; head += 8) {
        float* base = (head < NH)
            ? g_qg + (size_t)t * QGN + head * HD
            : g_k  + (size_t)t * KVN + (head - NH) * HD;
        float x0 = base[lane];
        float x1 = base[lane + 32];
        float p0 = base[64 + lane];
        float p1 = base[96 + lane];
        float rh0 = -x1;
        float rh1 = x0;
        if (head < NH) {
            base[lane]      = c0 * p0 + rh0 * s0;
            base[lane + 32] = c1 * p1 + rh1 * s1;
        } else {
            base[lane]      = __uint_as_float(f2tf32(s0 * p0 + rh0 * s0));
            base[lane + 32] = __uint_as_float(f2tf32(s1 * p1 + rh1 * s1));
        }
    }
}

// =============== flash attention, tf32 tensor cores ========================
// CTA 128 q-rows x 64 k-cols, 8 warps (warp = 16 rows).
// Q fragments in registers; K/V cp.async double-buffered (raw tf32 bits);
// P re-layout via quad shuffles (no smem); V row-major stride 136.
#define TSTR 136
#define QTILE (128 * TSTR)            // 17408 floats
#define KVTILE (64 * TSTR)            // 8704 floats
#define ATT_SMEM ((QTILE + 2 * 2 * KVTILE) * 4)   // 208896 B

__global__ __launch_bounds__(256) void attn_mma_kernel()
{
    extern __shared__ float sm[];

    const int qt  = (int)gridDim.x - 1 - (int)blockIdx.x;   // LPT: big CTAs first
    const int h   = blockIdx.y;
    const int b   = blockIdx.z;
    const int kvh = h / (NH / NKV);

    const int tid  = threadIdx.x;
    const int lane = tid & 31;
    const int wid  = tid >> 5;
    const int grp  = lane >> 2;
    const int tg   = lane & 3;
    const int wm   = wid * 16;

    const unsigned smb = (unsigned)__cvta_generic_to_shared(sm);
    const int njt = 2 * qt + 2;

    // ---- prologue: cp.async Q tile + K/V tile for jt=0 (group G0) ----
    const float* Qb = g_qg + (size_t)(b * SEQ + qt * 128) * QGN + h * HD;
#pragma unroll
    for (int i = 0; i < 16; i++) {
        int c = tid + i * 256;            // 0..4095
        int r = c >> 5;
        int cl = (c & 31) * 4;
        cp16(smb + (r * TSTR + cl) * 4, Qb + (size_t)r * QGN + cl);
    }
    {
        const float* Kb = g_k + (size_t)(b * SEQ) * KVN + kvh * HD;
        const float* Vb = g_v + (size_t)(b * SEQ) * KVN + kvh * HD;
#pragma unroll
        for (int i = 0; i < 8; i++) {
            int c = tid + i * 256;        // 0..2047
            int r = c >> 5;
            int cl = (c & 31) * 4;
            cp16(smb + (QTILE + r * TSTR + cl) * 4,          Kb + (size_t)r * KVN + cl);
            cp16(smb + (QTILE + KVTILE + r * TSTR + cl) * 4, Vb + (size_t)r * KVN + cl);
        }
    }
    asm volatile("cp.async.commit_group;\n");

    float o[16][4];
#pragma unroll
    for (int nt = 0; nt < 16; nt++)
#pragma unroll
        for (int c = 0; c < 4; c++) o[nt][c] = 0.0f;
    float m0 = -1e30f, m1 = -1e30f, l0 = 0.0f, l1 = 0.0f;
    unsigned qf[16][4];

    const float scale = 0.08838834764831845f;   // 1/sqrt(128)
    const int row_g0 = qt * 128 + wm + grp;
    const int row_g1 = row_g0 + 8;
    const unsigned src_lo = (unsigned)((lane & ~3) | (tg >> 1));
    const unsigned src_hi = src_lo | 2u;
    const bool odd = (tg & 1);

    for (int jt = 0; jt < njt; jt++) {
        const int cs = jt & 1;
        // prefetch next K/V into the other stage (safe: end-of-iter sync below)
        if (jt + 1 < njt) {
            const int ns = 1 - cs;
            const float* Kb = g_k + (size_t)(b * SEQ + (jt + 1) * 64) * KVN + kvh * HD;
            const float* Vb = g_v + (size_t)(b * SEQ + (jt + 1) * 64) * KVN + kvh * HD;
            unsigned kofs = smb + (QTILE + ns * 2 * KVTILE) * 4;
#pragma unroll
            for (int i = 0; i < 8; i++) {
                int c = tid + i * 256;
                int r = c >> 5;
                int cl = (c & 31) * 4;
                cp16(kofs + (r * TSTR + cl) * 4,            Kb + (size_t)r * KVN + cl);
                cp16(kofs + (KVTILE + r * TSTR + cl) * 4,   Vb + (size_t)r * KVN + cl);
            }
        }
        asm volatile("cp.async.commit_group;\n");
        asm volatile("cp.async.wait_group 1;\n");
        __syncthreads();

        const float* Ks = sm + QTILE + cs * 2 * KVTILE;
        const float* Vs = Ks + KVTILE;

        if (jt == 0) {
            // Q fragments -> registers (raw fp32 in smem; round once here)
            const float* Qs = sm;
#pragma unroll
            for (int ks = 0; ks < 16; ks++) {
                int k0 = ks * 8;
                qf[ks][0] = f2tf32(Qs[(wm + grp)     * TSTR + k0 + tg]);
                qf[ks][1] = f2tf32(Qs[(wm + grp + 8) * TSTR + k0 + tg]);
                qf[ks][2] = f2tf32(Qs[(wm + grp)     * TSTR + k0 + tg + 4]);
                qf[ks][3] = f2tf32(Qs[(wm + grp + 8) * TSTR + k0 + tg + 4]);
            }
        }

        // ---- S = Q @ K^T (K bits already tf32-rounded in global) ----
        float s[8][4];
#pragma unroll
        for (int nt = 0; nt < 8; nt++)
#pragma unroll
            for (int c = 0; c < 4; c++) s[nt][c] = 0.0f;

#pragma unroll
        for (int ks = 0; ks < 16; ks++) {
            int k0 = ks * 8;
#pragma unroll
            for (int nt = 0; nt < 8; nt++) {
                unsigned b0 = __float_as_uint(Ks[(nt * 8 + grp) * TSTR + k0 + tg]);
                unsigned b1 = __float_as_uint(Ks[(nt * 8 + grp) * TSTR + k0 + tg + 4]);
                MMA_TF32(s[nt][0], s[nt][1], s[nt][2], s[nt][3],
                         qf[ks][0], qf[ks][1], qf[ks][2], qf[ks][3], b0, b1);
            }
        }

        // ---- scale + causal mask (diagonal tiles only) ----
        const bool need_mask = (jt >= 2 * qt);
#pragma unroll
        for (int nt = 0; nt < 8; nt++) {
            s[nt][0] *= scale; s[nt][1] *= scale;
            s[nt][2] *= scale; s[nt][3] *= scale;
            if (need_mask) {
                int c0 = jt * 64 + nt * 8 + 2 * tg;
                if (c0     > row_g0) s[nt][0] = -1.0e9f;
                if (c0 + 1 > row_g0) s[nt][1] = -1.0e9f;
                if (c0     > row_g1) s[nt][2] = -1.0e9f;
                if (c0 + 1 > row_g1) s[nt][3] = -1.0e9f;
            }
        }

        // ---- online softmax (rows warp-local; quad reduction) ----
        float mx0 = -1e30f, mx1 = -1e30f;
#pragma unroll
        for (int nt = 0; nt < 8; nt++) {
            mx0 = fmaxf(mx0, fmaxf(s[nt][0], s[nt][1]));
            mx1 = fmaxf(mx1, fmaxf(s[nt][2], s[nt][3]));
        }
        mx0 = fmaxf(mx0, __shfl_xor_sync(0xffffffffu, mx0, 1));
        mx0 = fmaxf(mx0, __shfl_xor_sync(0xffffffffu, mx0, 2));
        mx1 = fmaxf(mx1, __shfl_xor_sync(0xffffffffu, mx1, 1));
        mx1 = fmaxf(mx1, __shfl_xor_sync(0xffffffffu, mx1, 2));

        float mn0 = fmaxf(m0, mx0);
        float mn1 = fmaxf(m1, mx1);
        float sc0 = __expf(m0 - mn0);
        float sc1 = __expf(m1 - mn1);
        float rs0 = 0.0f, rs1 = 0.0f;
#pragma unroll
        for (int nt = 0; nt < 8; nt++) {
            s[nt][0] = __expf(s[nt][0] - mn0);
            s[nt][1] = __expf(s[nt][1] - mn0);
            s[nt][2] = __expf(s[nt][2] - mn1);
            s[nt][3] = __expf(s[nt][3] - mn1);
            rs0 += s[nt][0] + s[nt][1];
            rs1 += s[nt][2] + s[nt][3];
        }
        rs0 += __shfl_xor_sync(0xffffffffu, rs0, 1);
        rs0 += __shfl_xor_sync(0xffffffffu, rs0, 2);
        rs1 += __shfl_xor_sync(0xffffffffu, rs1, 1);
        rs1 += __shfl_xor_sync(0xffffffffu, rs1, 2);

        l0 = l0 * sc0 + rs0; m0 = mn0;
        l1 = l1 * sc1 + rs1; m1 = mn1;
#pragma unroll
        for (int nt = 0; nt < 16; nt++) {
            o[nt][0] *= sc0; o[nt][1] *= sc0;
            o[nt][2] *= sc1; o[nt][3] *= sc1;
        }

        // ---- P: C-fragment -> A-fragment via quad shuffles (no smem) ----
        unsigned u[8][4];
#pragma unroll
        for (int nt = 0; nt < 8; nt++)
#pragma unroll
            for (int c = 0; c < 4; c++) u[nt][c] = f2tf32(s[nt][c]);

#pragma unroll
        for (int ks = 0; ks < 8; ks++) {
            unsigned t00 = __shfl_sync(0xffffffffu, u[ks][0], src_lo);
            unsigned t01 = __shfl_sync(0xffffffffu, u[ks][1], src_lo);
            unsigned a0  = odd ? t01 : t00;
            unsigned t10 = __shfl_sync(0xffffffffu, u[ks][2], src_lo);
            unsigned t11 = __shfl_sync(0xffffffffu, u[ks][3], src_lo);
            unsigned a1  = odd ? t11 : t10;
            unsigned t20 = __shfl_sync(0xffffffffu, u[ks][0], src_hi);
            unsigned t21 = __shfl_sync(0xffffffffu, u[ks][1], src_hi);
            unsigned a2  = odd ? t21 : t20;
            unsigned t30 = __shfl_sync(0xffffffffu, u[ks][2], src_hi);
            unsigned t31 = __shfl_sync(0xffffffffu, u[ks][3], src_hi);
            unsigned a3  = odd ? t31 : t30;
            int k0 = ks * 8;
#pragma unroll
            for (int nt = 0; nt < 16; nt++) {
                unsigned b0 = __float_as_uint(Vs[(k0 + tg)     * TSTR + nt * 8 + grp]);
                unsigned b1 = __float_as_uint(Vs[(k0 + tg + 4) * TSTR + nt * 8 + grp]);
                MMA_TF32(o[nt][0], o[nt][1], o[nt][2], o[nt][3], a0, a1, a2, a3, b0, b1);
            }
        }
        __syncthreads();   // all warps done with stage cs before it is re-filled
    }

    // ---- epilogue: normalize, write g_o[token][h*128 + d] ----
    float inv0 = 1.0f / l0;
    float inv1 = 1.0f / l1;
#pragma unroll
    for (int nt = 0; nt < 16; nt++) {
        int col = h * HD + nt * 8 + 2 * tg;
        *(float2*)(g_o + (size_t)(b * SEQ + row_g0) * HID + col) =
            make_float2(o[nt][0] * inv0, o[nt][1] * inv0);
        *(float2*)(g_o + (size_t)(b * SEQ + row_g1) * HID + col) =
            make_float2(o[nt][2] * inv1, o[nt][3] * inv1);
    }
}

// ---------------- rmsnorm * (1+w) * sigmoid(gate) --------------------------
__global__ __launch_bounds__(256) void norm_gate_kernel(const float* __restrict__ nw)
{
    const int t   = blockIdx.x;
    const int tid = threadIdx.x;
    const float* o    = g_o  + (size_t)t * HID;
    const float* gate = g_qg + (size_t)t * QGN + 2048;

    float vals[8];
    float ss = 0.0f;
#pragma unroll
    for (int i = 0; i < 8; i++) {
        float v = o[tid + i * 256];
        vals[i] = v;
        ss += v * v;
    }
#pragma unroll
    for (int off = 16; off >= 1; off >>= 1)
        ss += __shfl_xor_sync(0xffffffffu, ss, off);

    __shared__ float red[8];
    if ((tid & 31) == 0) red[tid >> 5] = ss;
    __syncthreads();
    float tot = red[0] + red[1] + red[2] + red[3] + red[4] + red[5] + red[6] + red[7];
    float r = rsqrtf(tot / (float)HID + 1e-6f);

#pragma unroll
    for (int i = 0; i < 8; i++) {
        int j = tid + i * 256;
        float gt = gate[j];
        float sg = 1.0f / (1.0f + __expf(-gt));
        g_n[(size_t)t * HID + j] = vals[i] * r * (1.0f + nw[j]) * sg;
    }
}

// ---------------- launch ---------------------------------------------------
extern "C" void kernel_launch(void* const* d_in, const int* in_sizes, int n_in,
                              void* d_out, int out_size)
{
    const float* hs   = (const float*)d_in[0];
    const float* cosb = (const float*)d_in[1];
    const float* sinb = (const float*)d_in[2];
    // d_in[3] = attention_mask (causal, reproduced analytically)
    const float* Wq   = (const float*)d_in[4];
    const float* Wk   = (const float*)d_in[5];
    const float* Wv   = (const float*)d_in[6];
    const float* Wo   = (const float*)d_in[7];
    const float* nw   = (const float*)d_in[8];
    float* out = (float*)d_out;

    float *qg, *kb, *vb, *nb;
    cudaGetSymbolAddress((void**)&qg, g_qg);
    cudaGetSymbolAddress((void**)&kb, g_k);
    cudaGetSymbolAddress((void**)&vb, g_v);
    cudaGetSymbolAddress((void**)&nb, g_n);

    dim3 blk(256);

    cudaFuncSetAttribute(gemm_tf32, cudaFuncAttributeMaxDynamicSharedMemorySize, GEMM_SMEM);
    cudaFuncSetAttribute(attn_mma_kernel, cudaFuncAttributeMaxDynamicSharedMemorySize, ATT_SMEM);

    // 1) projections; KV outputs rounded to tf32 bits (rnd=1)
    gemm_tf32<<<dim3(QGN / TBN, NTOK / TBM, 1), blk, GEMM_SMEM>>>(
        hs, Wq, qg, Wq, qg, NTOK, QGN, HID, 0);
    gemm_tf32<<<dim3(KVN / TBN, NTOK / TBM, 2), blk, GEMM_SMEM>>>(
        hs, Wk, kb, Wv, vb, NTOK, KVN, HID, 1);

    // 2) rope (K outputs tf32-rounded)
    rope_kernel<<<NTOK, blk>>>(cosb, sinb);

    // 3) flash attention (cp.async double-buffered, shuffle-P)
    attn_mma_kernel<<<dim3(SEQ / 128, NH, BATCH), blk, ATT_SMEM>>>();

    // 4) rmsnorm * sigmoid(gate)
    norm_gate_kernel<<<NTOK, blk>>>(nw);

    // 5) output projection
    gemm_tf32<<<dim3(HID / TBN, NTOK / TBM, 1), blk, GEMM_SMEM>>>(
        nb, Wo, out, Wo, out, NTOK, HID, HID, 0);
}